// round 6
// baseline (speedup 1.0000x reference)
#include <cuda_runtime.h>
#include <cstdint>
#include <math.h>

#define N_DIM 1024
#define K_DIM 1024
#define NELEM 33554432  // 4*8192*1024

#define MT 128
#define NT 128
#define KT 32
#define STAGES 3
#define STAGE_BYTES 32768                 // A 16KB + B 16KB
#define SMEM_TOTAL (STAGES * STAGE_BYTES) // 96KB

// Scratch (device globals; no allocation allowed)
__device__ float g_K [NELEM];
__device__ float g_V [NELEM];
__device__ float g_Q [NELEM];
__device__ float g_KP[NELEM];
__device__ float g_QP[NELEM];
__device__ float g_R [NELEM];
__device__ float g_X [NELEM];
__device__ float g_WT[6 * 1024 * 1024];
__device__ float2 g_stats[32768];
__device__ float g_gWo[1024];
__device__ float g_bWoBo[1024];

// ---------------- helpers ----------------
__device__ __forceinline__ unsigned f2tf32(float f) {
    unsigned u;
    asm("cvt.rna.tf32.f32 %0, %1;" : "=r"(u) : "f"(f));
    return u;
}
__device__ __forceinline__ float rnd32(float f) { return __uint_as_float(f2tf32(f)); }

__device__ __forceinline__ uint32_t smem_u32(const void* p) {
    uint32_t a;
    asm("{ .reg .u64 t; cvta.to.shared.u64 t, %1; cvt.u32.u64 %0, t; }" : "=r"(a) : "l"(p));
    return a;
}
__device__ __forceinline__ void cp16(uint32_t dst, const void* src) {
    asm volatile("cp.async.cg.shared.global [%0], [%1], 16;\n" :: "r"(dst), "l"(src) : "memory");
}
__device__ __forceinline__ void cp_commit() {
    asm volatile("cp.async.commit_group;\n" ::: "memory");
}
template <int N> __device__ __forceinline__ void cp_wait() {
    asm volatile("cp.async.wait_group %0;\n" :: "n"(N) : "memory");
}
__device__ __forceinline__ void ldmx4(uint32_t& r0, uint32_t& r1, uint32_t& r2, uint32_t& r3,
                                      uint32_t addr) {
    asm volatile("ldmatrix.sync.aligned.m8n8.x4.shared.b16 {%0,%1,%2,%3}, [%4];"
                 : "=r"(r0), "=r"(r1), "=r"(r2), "=r"(r3) : "r"(addr));
}
__device__ __forceinline__ void mma_tf32(float c[4],
    uint32_t a0, uint32_t a1, uint32_t a2, uint32_t a3, uint32_t b0, uint32_t b1)
{
    asm volatile(
        "mma.sync.aligned.m16n8k8.row.col.f32.tf32.tf32.f32 "
        "{%0,%1,%2,%3}, {%4,%5,%6,%7}, {%8,%9}, {%0,%1,%2,%3};\n"
        : "+f"(c[0]), "+f"(c[1]), "+f"(c[2]), "+f"(c[3])
        : "r"(a0), "r"(a1), "r"(a2), "r"(a3), "r"(b0), "r"(b1));
}

struct GArgs {
    const float* A0; const float* A1; const float* A2;
    const float* W0; const float* W1; const float* W2;
    const float* b0; const float* b1; const float* b2;
    float* C0; float* C1; float* C2;
    const float* extra;       // EPI1: phase_scale, EPI3: x residual
    const float2* stats;      // EPI3: (rstd, mu*rstd) per row
    const float* gWo;         // EPI3: g @ Wo
    int rnd0, rnd1, rnd2;
};

// ---------------- GEMM (z-batched) ----------------
// C[z][M,1024] = A[z] @ W[z]^T. A/W already tf32-rounded. W is [N rows, K cols].
// 256 threads (8 warps), warp tile 32x64, 3-stage cp.async, XOR-swizzled ldmatrix.
// EPI 0: C = acc + bias                       (+ optional tf32 round, per z)
// EPI 1: C = tanh(acc + bias) * extra[n]
// EPI 3: C = rstd*acc - mu_rstd*gWo[n] + bias[n] + extra[row*1024+n]
template <int EPI>
__global__ void __launch_bounds__(256, 2)
gemm_tc(const GArgs args)
{
    extern __shared__ char smem[];
    const uint32_t tileBase = smem_u32(smem);

    const int z = blockIdx.z;
    const float* A    = (z == 0) ? args.A0 : (z == 1) ? args.A1 : args.A2;
    const float* WT   = (z == 0) ? args.W0 : (z == 1) ? args.W1 : args.W2;
    const float* bias = (z == 0) ? args.b0 : (z == 1) ? args.b1 : args.b2;
    float*       C    = (z == 0) ? args.C0 : (z == 1) ? args.C1 : args.C2;
    const int    rnd  = (z == 0) ? args.rnd0 : (z == 1) ? args.rnd1 : args.rnd2;

    const int tid  = threadIdx.x;
    const int wid  = tid >> 5;
    const int lane = tid & 31;
    const int wm   = wid >> 1;        // 0..3 : 32-row strip
    const int wn   = wid & 1;         // 0..1 : 64-col strip
    const int g    = lane >> 2;
    const int tg   = lane & 3;

    const long bm0 = (long)blockIdx.y * MT;
    const int  bn0 = blockIdx.x * NT;

    const float* Abase = A  + bm0 * K_DIM;
    const float* Bbase = WT + (long)bn0 * K_DIM;

    // ldmatrix geometry: rows 128B apart, 16B chunks XOR-swizzled by row&7
    const uint32_t rsw   = lane & 7;
    const uint32_t aoff0 = (uint32_t)((wm * 32 + ((lane >> 3) & 1) * 8 + (lane & 7)) * 128);
    const uint32_t hbitA = (lane >> 4) & 1;
    const uint32_t boff0 = (uint32_t)((wn * 64 + ((lane >> 4) & 1) * 8 + (lane & 7)) * 128) + 16384u;
    const uint32_t hbitB = (lane >> 3) & 1;

    auto fill = [&](int s) {
        const uint32_t buf = tileBase + (uint32_t)(s % STAGES) * STAGE_BYTES;
        const int k0 = s * KT;
        #pragma unroll
        for (int i = 0; i < 4; i++) {          // A: 128 rows x 8 chunks
            int o = tid + 256 * i;
            int row = o >> 3, c = o & 7;
            cp16(buf + (uint32_t)(row * 128 + ((c ^ (row & 7)) << 4)),
                 Abase + row * K_DIM + k0 + c * 4);
        }
        #pragma unroll
        for (int i = 0; i < 4; i++) {          // B
            int o = tid + 256 * i;
            int row = o >> 3, c = o & 7;
            cp16(buf + 16384u + (uint32_t)(row * 128 + ((c ^ (row & 7)) << 4)),
                 Bbase + row * K_DIM + k0 + c * 4);
        }
        cp_commit();
    };

    float acc[2][8][4];
    #pragma unroll
    for (int i = 0; i < 2; i++)
        #pragma unroll
        for (int j = 0; j < 8; j++)
            #pragma unroll
            for (int k = 0; k < 4; k++)
                acc[i][j][k] = 0.f;

    fill(0);
    fill(1);

    #pragma unroll 1
    for (int kt = 0; kt < 32; kt++) {
        if (kt < 31) cp_wait<1>(); else cp_wait<0>();
        __syncthreads();
        if (kt < 30) fill(kt + 2);

        const uint32_t sbase = tileBase + (uint32_t)(kt % STAGES) * STAGE_BYTES;
        #pragma unroll
        for (int kk = 0; kk < 4; kk++) {
            uint32_t af[2][4], bf[8][2];
            const uint32_t cA = ((uint32_t)(kk * 2) + hbitA) ^ rsw;
            const uint32_t cB = ((uint32_t)(kk * 2) + hbitB) ^ rsw;
            ldmx4(af[0][0], af[0][1], af[0][2], af[0][3], sbase + aoff0 + (cA << 4));
            ldmx4(af[1][0], af[1][1], af[1][2], af[1][3], sbase + aoff0 + 2048u + (cA << 4));
            #pragma unroll
            for (int q = 0; q < 4; q++)
                ldmx4(bf[2 * q][0], bf[2 * q][1], bf[2 * q + 1][0], bf[2 * q + 1][1],
                      sbase + boff0 + (uint32_t)(q * 2048) + (cB << 4));
            #pragma unroll
            for (int im = 0; im < 2; im++)
                #pragma unroll
                for (int in = 0; in < 8; in++)
                    mma_tf32(acc[im][in],
                             af[im][0], af[im][1], af[im][2], af[im][3],
                             bf[in][0], bf[in][1]);
        }
    }

    // Epilogue
    #pragma unroll
    for (int im = 0; im < 2; im++) {
        #pragma unroll
        for (int in = 0; in < 8; in++) {
            const int col = bn0 + wn * 64 + in * 8 + 2 * tg;
            const float b0 = __ldg(bias + col);
            const float b1 = __ldg(bias + col + 1);
            #pragma unroll
            for (int h = 0; h < 2; h++) {
                const long row = bm0 + wm * 32 + im * 16 + g + h * 8;
                float v0, v1;
                if (EPI == 3) {
                    const float2 st = __ldg(args.stats + row);
                    const float gw0 = __ldg(args.gWo + col);
                    const float gw1 = __ldg(args.gWo + col + 1);
                    v0 = st.x * acc[im][in][2 * h + 0] - st.y * gw0 + b0
                         + args.extra[row * N_DIM + col];
                    v1 = st.x * acc[im][in][2 * h + 1] - st.y * gw1 + b1
                         + args.extra[row * N_DIM + col + 1];
                } else {
                    v0 = acc[im][in][2 * h + 0] + b0;
                    v1 = acc[im][in][2 * h + 1] + b1;
                    if (EPI == 1) {
                        v0 = tanhf(v0) * __ldg(args.extra + col);
                        v1 = tanhf(v1) * __ldg(args.extra + col + 1);
                    }
                    if (rnd) { v0 = rnd32(v0); v1 = rnd32(v1); }
                }
                *(float2*)(C + row * N_DIM + col) = make_float2(v0, v1);
            }
        }
    }
}

// ---------------- prep kernels ----------------
struct W6 { const float* w[6]; };

__global__ void __launch_bounds__(256)
wtrans_all_k(const W6 ws, float* __restrict__ WT)
{
    __shared__ float t[32][33];
    const float* W = ws.w[blockIdx.z];
    float* D = WT + (long)blockIdx.z * 1048576;
    int bx = blockIdx.x * 32, by = blockIdx.y * 32;
    #pragma unroll
    for (int i = threadIdx.y; i < 32; i += 8)
        t[i][threadIdx.x] = W[(by + i) * 1024 + bx + threadIdx.x];
    __syncthreads();
    #pragma unroll
    for (int i = threadIdx.y; i < 32; i += 8)
        D[(bx + i) * 1024 + by + threadIdx.x] = rnd32(t[threadIdx.x][i]);
}

__global__ void __launch_bounds__(256)
round_x_k(const float* __restrict__ x, float* __restrict__ o)
{
    long i = ((long)blockIdx.x * 256 + threadIdx.x) * 4;
    float4 v = *(const float4*)(x + i);
    v.x = rnd32(v.x); v.y = rnd32(v.y); v.z = rnd32(v.z); v.w = rnd32(v.w);
    *(float4*)(o + i) = v;
}

// gWo[col] = sum_d g[d]*Wo[d,col];  bWoBo[col] = sum_d b[d]*Wo[d,col] + bo[col]
__global__ void __launch_bounds__(256)
gemv_prep_k(const float* __restrict__ Wo, const float* __restrict__ g,
            const float* __restrict__ b, const float* __restrict__ bo,
            float* __restrict__ gWo, float* __restrict__ bWoBo)
{
    int col = blockIdx.x * 256 + threadIdx.x;
    float a1 = 0.f, a2 = 0.f;
    for (int d = 0; d < 1024; d++) {
        float w = Wo[(long)d * 1024 + col];
        a1 = fmaf(__ldg(g + d), w, a1);
        a2 = fmaf(__ldg(b + d), w, a2);
    }
    gWo[col] = a1;
    bWoBo[col] = a2 + bo[col];
}

// ---------------- bind + chunk scan + row stats + gamma fold ----------------
// R = rnd32(retrieved * ln_g);  stats[row] = (rstd, mu*rstd) of retrieved
__global__ void __launch_bounds__(256)
bind_scan_k(const float* __restrict__ V, const float* __restrict__ KP,
            const float* __restrict__ QP, const float* __restrict__ lng,
            float* __restrict__ R, float2* __restrict__ stats)
{
    __shared__ float2 part[64][8];
    const float inv = 0.03125f;  // 1/sqrt(1024)
    const int tid = threadIdx.x;
    const int lane = tid & 31, w = tid >> 5;
    long idx = (long)blockIdx.x * 64 * 1024 + tid * 4;
    float4 mr = make_float4(0.f, 0.f, 0.f, 0.f);
    float4 mi = make_float4(0.f, 0.f, 0.f, 0.f);
    const float4 gv = *(const float4*)(lng + tid * 4);

    #pragma unroll 4
    for (int s = 0; s < 64; s++, idx += 1024) {
        float4 v  = *(const float4*)(V + idx);
        float4 kp = *(const float4*)(KP + idx);
        float4 qp = *(const float4*)(QP + idx);
        float4 out;
        float sk, ck, sq, cq;
        __sincosf(kp.x, &sk, &ck);
        mr.x = fmaf(v.x, ck, mr.x); mi.x = fmaf(v.x, sk, mi.x);
        __sincosf(qp.x, &sq, &cq);
        out.x = (mr.x * cq + mi.x * sq) * inv;
        __sincosf(kp.y, &sk, &ck);
        mr.y = fmaf(v.y, ck, mr.y); mi.y = fmaf(v.y, sk, mi.y);
        __sincosf(qp.y, &sq, &cq);
        out.y = (mr.y * cq + mi.y * sq) * inv;
        __sincosf(kp.z, &sk, &ck);
        mr.z = fmaf(v.z, ck, mr.z); mi.z = fmaf(v.z, sk, mi.z);
        __sincosf(qp.z, &sq, &cq);
        out.z = (mr.z * cq + mi.z * sq) * inv;
        __sincosf(kp.w, &sk, &ck);
        mr.w = fmaf(v.w, ck, mr.w); mi.w = fmaf(v.w, sk, mi.w);
        __sincosf(qp.w, &sq, &cq);
        out.w = (mr.w * cq + mi.w * sq) * inv;

        // row stats partials (on retrieved, pre-gamma)
        float rs = out.x + out.y + out.z + out.w;
        float rq = out.x * out.x + out.y * out.y + out.z * out.z + out.w * out.w;
        #pragma unroll
        for (int o = 16; o; o >>= 1) {
            rs += __shfl_xor_sync(0xffffffffu, rs, o);
            rq += __shfl_xor_sync(0xffffffffu, rq, o);
        }
        if (lane == 0) part[s][w] = make_float2(rs, rq);

        // write gamma-folded tf32 value
        out.x = rnd32(out.x * gv.x);
        out.y = rnd32(out.y * gv.y);
        out.z = rnd32(out.z * gv.z);
        out.w = rnd32(out.w * gv.w);
        *(float4*)(R + idx) = out;
    }
    __syncthreads();
    if (tid < 64) {
        float S = 0.f, Q = 0.f;
        #pragma unroll
        for (int i = 0; i < 8; i++) { S += part[tid][i].x; Q += part[tid][i].y; }
        float mu = S * (1.f / 1024.f);
        float var = Q * (1.f / 1024.f) - mu * mu;
        float rstd = rsqrtf(var + 1e-5f);
        stats[blockIdx.x * 64 + tid] = make_float2(rstd, mu * rstd);
    }
}

extern "C" void kernel_launch(void* const* d_in, const int* in_sizes, int n_in,
                              void* d_out, int out_size)
{
    const float* x   = (const float*)d_in[0];
    const float* Wk  = (const float*)d_in[1];
    const float* bk  = (const float*)d_in[2];
    const float* Wv  = (const float*)d_in[3];
    const float* bv  = (const float*)d_in[4];
    const float* Wq  = (const float*)d_in[5];
    const float* bq  = (const float*)d_in[6];
    const float* Wkp = (const float*)d_in[7];
    const float* bkp = (const float*)d_in[8];
    const float* Wqp = (const float*)d_in[9];
    const float* bqp = (const float*)d_in[10];
    const float* ps  = (const float*)d_in[11];
    const float* lng = (const float*)d_in[12];
    const float* lnb = (const float*)d_in[13];
    const float* Wo  = (const float*)d_in[14];
    const float* bo  = (const float*)d_in[15];
    float* out = (float*)d_out;

    const int M = in_sizes[0] / 1024;  // 32768

    float *pK, *pV, *pQ, *pKP, *pQP, *pR, *pX, *pWT, *pgWo, *pbWoBo;
    float2* pStats;
    cudaGetSymbolAddress((void**)&pK,  g_K);
    cudaGetSymbolAddress((void**)&pV,  g_V);
    cudaGetSymbolAddress((void**)&pQ,  g_Q);
    cudaGetSymbolAddress((void**)&pKP, g_KP);
    cudaGetSymbolAddress((void**)&pQP, g_QP);
    cudaGetSymbolAddress((void**)&pR,  g_R);
    cudaGetSymbolAddress((void**)&pX,  g_X);
    cudaGetSymbolAddress((void**)&pWT, g_WT);
    cudaGetSymbolAddress((void**)&pStats, g_stats);
    cudaGetSymbolAddress((void**)&pgWo, g_gWo);
    cudaGetSymbolAddress((void**)&pbWoBo, g_bWoBo);

    cudaFuncSetAttribute(gemm_tc<0>, cudaFuncAttributeMaxDynamicSharedMemorySize, SMEM_TOTAL);
    cudaFuncSetAttribute(gemm_tc<1>, cudaFuncAttributeMaxDynamicSharedMemorySize, SMEM_TOTAL);
    cudaFuncSetAttribute(gemm_tc<3>, cudaFuncAttributeMaxDynamicSharedMemorySize, SMEM_TOTAL);

    // prep
    W6 ws;
    ws.w[0] = Wk; ws.w[1] = Wv; ws.w[2] = Wq; ws.w[3] = Wkp; ws.w[4] = Wqp; ws.w[5] = Wo;
    wtrans_all_k<<<dim3(32, 32, 6), dim3(32, 8)>>>(ws, pWT);
    round_x_k<<<NELEM / 1024, 256>>>(x, pX);
    gemv_prep_k<<<4, 256>>>(Wo, lng, lnb, bo, pgWo, pbWoBo);

    GArgs a{};

    // QKV fused (z=3)
    a.A0 = pX; a.A1 = pX; a.A2 = pX;
    a.W0 = pWT + 0 * 1048576; a.W1 = pWT + 1 * 1048576; a.W2 = pWT + 2 * 1048576;
    a.b0 = bk; a.b1 = bv; a.b2 = bq;
    a.C0 = pK; a.C1 = pV; a.C2 = pQ;
    a.rnd0 = 1; a.rnd1 = 0; a.rnd2 = 1;
    gemm_tc<0><<<dim3(N_DIM / NT, M / MT, 3), 256, SMEM_TOTAL>>>(a);

    // KP / QP fused (z=2)
    a.A0 = pK; a.A1 = pQ; a.A2 = pQ;
    a.W0 = pWT + 3 * 1048576; a.W1 = pWT + 4 * 1048576; a.W2 = a.W1;
    a.b0 = bkp; a.b1 = bqp; a.b2 = bqp;
    a.C0 = pKP; a.C1 = pQP; a.C2 = pQP;
    a.extra = ps;
    a.rnd0 = 0; a.rnd1 = 0; a.rnd2 = 0;
    gemm_tc<1><<<dim3(N_DIM / NT, M / MT, 2), 256, SMEM_TOTAL>>>(a);

    bind_scan_k<<<M / 64, 256>>>(pV, pKP, pQP, lng, pR, pStats);

    // Output GEMM with fused LayerNorm-affine + residual (z=1)
    a.A0 = pR; a.A1 = pR; a.A2 = pR;
    a.W0 = pWT + 5 * 1048576; a.W1 = a.W0; a.W2 = a.W0;
    a.b0 = pbWoBo; a.b1 = pbWoBo; a.b2 = pbWoBo;
    a.C0 = out; a.C1 = out; a.C2 = out;
    a.extra = x;
    a.stats = pStats;
    a.gWo = pgWo;
    gemm_tc<3><<<dim3(N_DIM / NT, M / MT, 1), 256, SMEM_TOTAL>>>(a);
}

// round 7
// speedup vs baseline: 1.1040x; 1.1040x over previous
#include <cuda_runtime.h>
#include <cstdint>
#include <math.h>

#define N_DIM 1024
#define K_DIM 1024
#define NELEM 33554432  // 4*8192*1024

#define MT 128
#define NT 128
#define KT 32
#define STAGES 3
#define STAGE_BYTES 32768                 // A 16KB + B 16KB
#define SMEM_TOTAL (STAGES * STAGE_BYTES) // 96KB

// Scratch (device globals; zero-initialized)
__device__ float g_WkR[1048576];
__device__ float g_WqR[1048576];
__device__ float g_V [NELEM];
__device__ float g_KP[NELEM];
__device__ float g_QP[NELEM];
__device__ float g_R [NELEM];
__device__ float g_X [NELEM];
__device__ float g_WT[6 * 1024 * 1024];
__device__ float2 g_stats[32768];
__device__ float g_gWo[1024];
__device__ float g_bWoBo[1024];
__device__ float g_bck[1024];
__device__ float g_bcq[1024];
__device__ float g_zero[1024];

// ---------------- helpers ----------------
__device__ __forceinline__ unsigned f2tf32(float f) {
    unsigned u;
    asm("cvt.rna.tf32.f32 %0, %1;" : "=r"(u) : "f"(f));
    return u;
}
__device__ __forceinline__ float rnd32(float f) { return __uint_as_float(f2tf32(f)); }

__device__ __forceinline__ uint32_t smem_u32(const void* p) {
    uint32_t a;
    asm("{ .reg .u64 t; cvta.to.shared.u64 t, %1; cvt.u32.u64 %0, t; }" : "=r"(a) : "l"(p));
    return a;
}
__device__ __forceinline__ void cp16(uint32_t dst, const void* src) {
    asm volatile("cp.async.cg.shared.global [%0], [%1], 16;\n" :: "r"(dst), "l"(src) : "memory");
}
__device__ __forceinline__ void cp_commit() {
    asm volatile("cp.async.commit_group;\n" ::: "memory");
}
template <int N> __device__ __forceinline__ void cp_wait() {
    asm volatile("cp.async.wait_group %0;\n" :: "n"(N) : "memory");
}
__device__ __forceinline__ void ldmx4(uint32_t& r0, uint32_t& r1, uint32_t& r2, uint32_t& r3,
                                      uint32_t addr) {
    asm volatile("ldmatrix.sync.aligned.m8n8.x4.shared.b16 {%0,%1,%2,%3}, [%4];"
                 : "=r"(r0), "=r"(r1), "=r"(r2), "=r"(r3) : "r"(addr));
}
__device__ __forceinline__ void mma_tf32(float c[4],
    uint32_t a0, uint32_t a1, uint32_t a2, uint32_t a3, uint32_t b0, uint32_t b1)
{
    asm volatile(
        "mma.sync.aligned.m16n8k8.row.col.f32.tf32.tf32.f32 "
        "{%0,%1,%2,%3}, {%4,%5,%6,%7}, {%8,%9}, {%0,%1,%2,%3};\n"
        : "+f"(c[0]), "+f"(c[1]), "+f"(c[2]), "+f"(c[3])
        : "r"(a0), "r"(a1), "r"(a2), "r"(a3), "r"(b0), "r"(b1));
}

struct GArgs {
    const float* A[3];
    const float* W[3];
    const float* b[3];
    float*       C[3];
    int epi[3];               // 0: +bias  1: tanh(+bias)*ps  3: LN-affine+residual
    int rnd[3];               // tf32-round the result
    const float* ps;          // epi1
    const float* resid;       // epi3: x
    const float2* stats;      // epi3: (rstd, mu*rstd)
    const float* gWo;         // epi3
};

// ---------------- GEMM (z-batched, runtime epilogue) ----------------
// C[z][M,1024] = A[z] @ W[z]^T.  Operands pre-rounded to tf32.
// W is [N rows, K cols]. 256 threads, warp tile 32x64, 3-stage cp.async.
__global__ void __launch_bounds__(256, 2)
gemm_rt(const GArgs args)
{
    extern __shared__ char smem[];
    const uint32_t tileBase = smem_u32(smem);

    const int z = blockIdx.z;
    const float* A    = args.A[z];
    const float* WT   = args.W[z];
    const float* bias = args.b[z];
    float*       C    = args.C[z];
    const int    epi  = args.epi[z];
    const int    rnd  = args.rnd[z];

    const int tid  = threadIdx.x;
    const int wid  = tid >> 5;
    const int lane = tid & 31;
    const int wm   = wid >> 1;
    const int wn   = wid & 1;
    const int g    = lane >> 2;
    const int tg   = lane & 3;

    const long bm0 = (long)blockIdx.y * MT;
    const int  bn0 = blockIdx.x * NT;

    const float* Abase = A  + bm0 * K_DIM;
    const float* Bbase = WT + (long)bn0 * K_DIM;

    const uint32_t rsw   = lane & 7;
    const uint32_t aoff0 = (uint32_t)((wm * 32 + ((lane >> 3) & 1) * 8 + (lane & 7)) * 128);
    const uint32_t hbitA = (lane >> 4) & 1;
    const uint32_t boff0 = (uint32_t)((wn * 64 + ((lane >> 4) & 1) * 8 + (lane & 7)) * 128) + 16384u;
    const uint32_t hbitB = (lane >> 3) & 1;

    auto fill = [&](int s) {
        const uint32_t buf = tileBase + (uint32_t)(s % STAGES) * STAGE_BYTES;
        const int k0 = s * KT;
        #pragma unroll
        for (int i = 0; i < 4; i++) {
            int o = tid + 256 * i;
            int row = o >> 3, c = o & 7;
            cp16(buf + (uint32_t)(row * 128 + ((c ^ (row & 7)) << 4)),
                 Abase + row * K_DIM + k0 + c * 4);
        }
        #pragma unroll
        for (int i = 0; i < 4; i++) {
            int o = tid + 256 * i;
            int row = o >> 3, c = o & 7;
            cp16(buf + 16384u + (uint32_t)(row * 128 + ((c ^ (row & 7)) << 4)),
                 Bbase + row * K_DIM + k0 + c * 4);
        }
        cp_commit();
    };

    float acc[2][8][4];
    #pragma unroll
    for (int i = 0; i < 2; i++)
        #pragma unroll
        for (int j = 0; j < 8; j++)
            #pragma unroll
            for (int k = 0; k < 4; k++)
                acc[i][j][k] = 0.f;

    fill(0);
    fill(1);

    #pragma unroll 1
    for (int kt = 0; kt < 32; kt++) {
        if (kt < 31) cp_wait<1>(); else cp_wait<0>();
        __syncthreads();
        if (kt < 30) fill(kt + 2);

        const uint32_t sbase = tileBase + (uint32_t)(kt % STAGES) * STAGE_BYTES;
        #pragma unroll
        for (int kk = 0; kk < 4; kk++) {
            uint32_t af[2][4], bf[8][2];
            const uint32_t cA = ((uint32_t)(kk * 2) + hbitA) ^ rsw;
            const uint32_t cB = ((uint32_t)(kk * 2) + hbitB) ^ rsw;
            ldmx4(af[0][0], af[0][1], af[0][2], af[0][3], sbase + aoff0 + (cA << 4));
            ldmx4(af[1][0], af[1][1], af[1][2], af[1][3], sbase + aoff0 + 2048u + (cA << 4));
            #pragma unroll
            for (int q = 0; q < 4; q++)
                ldmx4(bf[2 * q][0], bf[2 * q][1], bf[2 * q + 1][0], bf[2 * q + 1][1],
                      sbase + boff0 + (uint32_t)(q * 2048) + (cB << 4));
            #pragma unroll
            for (int im = 0; im < 2; im++)
                #pragma unroll
                for (int in = 0; in < 8; in++)
                    mma_tf32(acc[im][in],
                             af[im][0], af[im][1], af[im][2], af[im][3],
                             bf[in][0], bf[in][1]);
        }
    }

    // Epilogue (runtime-selected, out of the hot loop)
    #pragma unroll
    for (int im = 0; im < 2; im++) {
        #pragma unroll
        for (int in = 0; in < 8; in++) {
            const int col = bn0 + wn * 64 + in * 8 + 2 * tg;
            const float b0 = __ldg(bias + col);
            const float b1 = __ldg(bias + col + 1);
            #pragma unroll
            for (int h = 0; h < 2; h++) {
                const long row = bm0 + wm * 32 + im * 16 + g + h * 8;
                float v0, v1;
                if (epi == 3) {
                    const float2 st = __ldg(args.stats + row);
                    v0 = st.x * acc[im][in][2 * h + 0] - st.y * __ldg(args.gWo + col) + b0
                         + args.resid[row * N_DIM + col];
                    v1 = st.x * acc[im][in][2 * h + 1] - st.y * __ldg(args.gWo + col + 1) + b1
                         + args.resid[row * N_DIM + col + 1];
                } else {
                    v0 = acc[im][in][2 * h + 0] + b0;
                    v1 = acc[im][in][2 * h + 1] + b1;
                    if (epi == 1) {
                        v0 = tanhf(v0) * __ldg(args.ps + col);
                        v1 = tanhf(v1) * __ldg(args.ps + col + 1);
                    }
                    if (rnd) { v0 = rnd32(v0); v1 = rnd32(v1); }
                }
                *(float2*)(C + row * N_DIM + col) = make_float2(v0, v1);
            }
        }
    }
}

// ---------------- prep kernels ----------------
struct W4 { const float* w[4]; };

__global__ void __launch_bounds__(256)
wtrans_all_k(const W4 ws, float* __restrict__ WT)
{
    __shared__ float t[32][33];
    static const int slot[4] = {0, 1, 2, 5};
    const float* W = ws.w[blockIdx.z];
    float* D = WT + (long)slot[blockIdx.z] * 1048576;
    int bx = blockIdx.x * 32, by = blockIdx.y * 32;
    #pragma unroll
    for (int i = threadIdx.y; i < 32; i += 8)
        t[i][threadIdx.x] = W[(by + i) * 1024 + bx + threadIdx.x];
    __syncthreads();
    #pragma unroll
    for (int i = threadIdx.y; i < 32; i += 8)
        D[(bx + i) * 1024 + by + threadIdx.x] = rnd32(t[threadIdx.x][i]);
}

__global__ void __launch_bounds__(256)
round_x_k(const float* __restrict__ x, float* __restrict__ o)
{
    long i = ((long)blockIdx.x * 256 + threadIdx.x) * 4;
    float4 v = *(const float4*)(x + i);
    v.x = rnd32(v.x); v.y = rnd32(v.y); v.z = rnd32(v.z); v.w = rnd32(v.w);
    *(float4*)(o + i) = v;
}

__global__ void __launch_bounds__(256)
round_w_k(const float* __restrict__ w0, const float* __restrict__ w1,
          float* __restrict__ o0, float* __restrict__ o1)
{
    const float* s = blockIdx.y ? w1 : w0;
    float* d = blockIdx.y ? o1 : o0;
    long i = ((long)blockIdx.x * 256 + threadIdx.x) * 4;
    float4 v = *(const float4*)(s + i);
    v.x = rnd32(v.x); v.y = rnd32(v.y); v.z = rnd32(v.z); v.w = rnd32(v.w);
    *(float4*)(d + i) = v;
}

// gWo = g@Wo ; bWoBo = b@Wo + bo ; bck = bk@Wkp + bkp ; bcq = bq@Wqp + bqp
__global__ void __launch_bounds__(256)
gemv_prep_k(const float* __restrict__ Wo, const float* __restrict__ g,
            const float* __restrict__ b, const float* __restrict__ bo,
            const float* __restrict__ Wkp, const float* __restrict__ bk,
            const float* __restrict__ bkp,
            const float* __restrict__ Wqp, const float* __restrict__ bq,
            const float* __restrict__ bqp,
            float* __restrict__ gWo, float* __restrict__ bWoBo,
            float* __restrict__ bck, float* __restrict__ bcq)
{
    int col = blockIdx.x * 256 + threadIdx.x;
    float a1 = 0.f, a2 = 0.f, a3 = 0.f, a4 = 0.f;
    for (int d = 0; d < 1024; d++) {
        float w = Wo[(long)d * 1024 + col];
        a1 = fmaf(__ldg(g + d), w, a1);
        a2 = fmaf(__ldg(b + d), w, a2);
        a3 = fmaf(__ldg(bk + d), Wkp[(long)d * 1024 + col], a3);
        a4 = fmaf(__ldg(bq + d), Wqp[(long)d * 1024 + col], a4);
    }
    gWo[col] = a1;
    bWoBo[col] = a2 + bo[col];
    bck[col] = a3 + bkp[col];
    bcq[col] = a4 + bqp[col];
}

// ---------------- bind + chunk scan + row stats + gamma fold ----------------
__global__ void __launch_bounds__(256)
bind_scan_k(const float* __restrict__ V, const float* __restrict__ KP,
            const float* __restrict__ QP, const float* __restrict__ lng,
            float* __restrict__ R, float2* __restrict__ stats)
{
    __shared__ float2 part[64][8];
    const float inv = 0.03125f;  // 1/sqrt(1024)
    const int tid = threadIdx.x;
    const int lane = tid & 31, w = tid >> 5;
    long idx = (long)blockIdx.x * 64 * 1024 + tid * 4;
    float4 mr = make_float4(0.f, 0.f, 0.f, 0.f);
    float4 mi = make_float4(0.f, 0.f, 0.f, 0.f);
    const float4 gv = *(const float4*)(lng + tid * 4);

    #pragma unroll 4
    for (int s = 0; s < 64; s++, idx += 1024) {
        float4 v  = *(const float4*)(V + idx);
        float4 kp = *(const float4*)(KP + idx);
        float4 qp = *(const float4*)(QP + idx);
        float4 out;
        float sk, ck, sq, cq;
        __sincosf(kp.x, &sk, &ck);
        mr.x = fmaf(v.x, ck, mr.x); mi.x = fmaf(v.x, sk, mi.x);
        __sincosf(qp.x, &sq, &cq);
        out.x = (mr.x * cq + mi.x * sq) * inv;
        __sincosf(kp.y, &sk, &ck);
        mr.y = fmaf(v.y, ck, mr.y); mi.y = fmaf(v.y, sk, mi.y);
        __sincosf(qp.y, &sq, &cq);
        out.y = (mr.y * cq + mi.y * sq) * inv;
        __sincosf(kp.z, &sk, &ck);
        mr.z = fmaf(v.z, ck, mr.z); mi.z = fmaf(v.z, sk, mi.z);
        __sincosf(qp.z, &sq, &cq);
        out.z = (mr.z * cq + mi.z * sq) * inv;
        __sincosf(kp.w, &sk, &ck);
        mr.w = fmaf(v.w, ck, mr.w); mi.w = fmaf(v.w, sk, mi.w);
        __sincosf(qp.w, &sq, &cq);
        out.w = (mr.w * cq + mi.w * sq) * inv;

        float rs = out.x + out.y + out.z + out.w;
        float rq = out.x * out.x + out.y * out.y + out.z * out.z + out.w * out.w;
        #pragma unroll
        for (int o = 16; o; o >>= 1) {
            rs += __shfl_xor_sync(0xffffffffu, rs, o);
            rq += __shfl_xor_sync(0xffffffffu, rq, o);
        }
        if (lane == 0) part[s][w] = make_float2(rs, rq);

        out.x = rnd32(out.x * gv.x);
        out.y = rnd32(out.y * gv.y);
        out.z = rnd32(out.z * gv.z);
        out.w = rnd32(out.w * gv.w);
        *(float4*)(R + idx) = out;
    }
    __syncthreads();
    if (tid < 64) {
        float S = 0.f, Q = 0.f;
        #pragma unroll
        for (int i = 0; i < 8; i++) { S += part[tid][i].x; Q += part[tid][i].y; }
        float mu = S * (1.f / 1024.f);
        float var = Q * (1.f / 1024.f) - mu * mu;
        float rstd = rsqrtf(var + 1e-5f);
        stats[blockIdx.x * 64 + tid] = make_float2(rstd, mu * rstd);
    }
}

extern "C" void kernel_launch(void* const* d_in, const int* in_sizes, int n_in,
                              void* d_out, int out_size)
{
    const float* x   = (const float*)d_in[0];
    const float* Wk  = (const float*)d_in[1];
    const float* bk  = (const float*)d_in[2];
    const float* Wv  = (const float*)d_in[3];
    const float* bv  = (const float*)d_in[4];
    const float* Wq  = (const float*)d_in[5];
    const float* bq  = (const float*)d_in[6];
    const float* Wkp = (const float*)d_in[7];
    const float* bkp = (const float*)d_in[8];
    const float* Wqp = (const float*)d_in[9];
    const float* bqp = (const float*)d_in[10];
    const float* ps  = (const float*)d_in[11];
    const float* lng = (const float*)d_in[12];
    const float* lnb = (const float*)d_in[13];
    const float* Wo  = (const float*)d_in[14];
    const float* bo  = (const float*)d_in[15];
    float* out = (float*)d_out;

    const int M = in_sizes[0] / 1024;  // 32768

    float *pV, *pKP, *pQP, *pR, *pX, *pWT, *pWkR, *pWqR;
    float *pgWo, *pbWoBo, *pbck, *pbcq, *pzero;
    float2* pStats;
    cudaGetSymbolAddress((void**)&pV,   g_V);
    cudaGetSymbolAddress((void**)&pKP,  g_KP);
    cudaGetSymbolAddress((void**)&pQP,  g_QP);
    cudaGetSymbolAddress((void**)&pR,   g_R);
    cudaGetSymbolAddress((void**)&pX,   g_X);
    cudaGetSymbolAddress((void**)&pWT,  g_WT);
    cudaGetSymbolAddress((void**)&pWkR, g_WkR);
    cudaGetSymbolAddress((void**)&pWqR, g_WqR);
    cudaGetSymbolAddress((void**)&pStats, g_stats);
    cudaGetSymbolAddress((void**)&pgWo, g_gWo);
    cudaGetSymbolAddress((void**)&pbWoBo, g_bWoBo);
    cudaGetSymbolAddress((void**)&pbck, g_bck);
    cudaGetSymbolAddress((void**)&pbcq, g_bcq);
    cudaGetSymbolAddress((void**)&pzero, g_zero);

    cudaFuncSetAttribute(gemm_rt, cudaFuncAttributeMaxDynamicSharedMemorySize, SMEM_TOTAL);

    // prep: transpose+round (Wv, Wkp, Wqp, Wo); round Wk, Wq; round x; biases
    W4 ws;
    ws.w[0] = Wv; ws.w[1] = Wkp; ws.w[2] = Wqp; ws.w[3] = Wo;
    wtrans_all_k<<<dim3(32, 32, 4), dim3(32, 8)>>>(ws, pWT);
    round_w_k<<<dim3(1024, 2), 256>>>(Wk, Wq, pWkR, pWqR);
    round_x_k<<<NELEM / 1024, 256>>>(x, pX);
    gemv_prep_k<<<4, 256>>>(Wo, lng, lnb, bo, Wkp, bk, bkp, Wqp, bq, bqp,
                            pgWo, pbWoBo, pbck, pbcq);

    GArgs a{};
    a.ps = ps; a.resid = x; a.stats = pStats; a.gWo = pgWo;

    // Weight composition: WckT = WkpT x WkR -> slot3 ; WcqT = WqpT x WqR -> slot4
    a.A[0] = pWT + 1 * 1048576; a.A[1] = pWT + 2 * 1048576; a.A[2] = a.A[1];
    a.W[0] = pWkR;              a.W[1] = pWqR;              a.W[2] = a.W[1];
    a.b[0] = pzero; a.b[1] = pzero; a.b[2] = pzero;
    a.C[0] = pWT + 3 * 1048576; a.C[1] = pWT + 4 * 1048576; a.C[2] = a.C[1];
    a.epi[0] = 0; a.epi[1] = 0; a.epi[2] = 0;
    a.rnd[0] = 1; a.rnd[1] = 1; a.rnd[2] = 1;
    gemm_rt<<<dim3(8, 8, 2), 256, SMEM_TOTAL>>>(a);

    // Big batch: V = X@WvT+bv ; KP = tanh(X@WckT+bck)*ps ; QP = tanh(X@WcqT+bcq)*ps
    a.A[0] = pX; a.A[1] = pX; a.A[2] = pX;
    a.W[0] = pWT + 0 * 1048576; a.W[1] = pWT + 3 * 1048576; a.W[2] = pWT + 4 * 1048576;
    a.b[0] = bv; a.b[1] = pbck; a.b[2] = pbcq;
    a.C[0] = pV; a.C[1] = pKP; a.C[2] = pQP;
    a.epi[0] = 0; a.epi[1] = 1; a.epi[2] = 1;
    a.rnd[0] = 0; a.rnd[1] = 0; a.rnd[2] = 0;
    gemm_rt<<<dim3(N_DIM / NT, M / MT, 3), 256, SMEM_TOTAL>>>(a);

    bind_scan_k<<<M / 64, 256>>>(pV, pKP, pQP, lng, pR, pStats);

    // Output GEMM with fused LayerNorm-affine + residual
    a.A[0] = pR; a.A[1] = pR; a.A[2] = pR;
    a.W[0] = pWT + 5 * 1048576; a.W[1] = a.W[0]; a.W[2] = a.W[0];
    a.b[0] = pbWoBo; a.b[1] = pbWoBo; a.b[2] = pbWoBo;
    a.C[0] = out; a.C[1] = out; a.C[2] = out;
    a.epi[0] = 3; a.epi[1] = 3; a.epi[2] = 3;
    a.rnd[0] = 0; a.rnd[1] = 0; a.rnd[2] = 0;
    gemm_rt<<<dim3(N_DIM / NT, M / MT, 1), 256, SMEM_TOTAL>>>(a);
}

// round 8
// speedup vs baseline: 1.4323x; 1.2974x over previous
#include <cuda_runtime.h>
#include <cstdint>
#include <math.h>

#define N_DIM 1024
#define K_DIM 1024
#define NELEM 33554432  // 4*8192*1024

#define MT 128
#define NT 128
#define KT 32
#define STAGES 3
#define STAGE_BYTES 32768                 // A 16KB + B 16KB
#define SMEM_TOTAL (STAGES * STAGE_BYTES) // 96KB

// Scratch (device globals; zero-initialized)
__device__ float g_WkR[1048576];
__device__ float g_WqR[1048576];
__device__ float g_V [NELEM];
__device__ float g_KP[NELEM];
__device__ float g_QP[NELEM];
__device__ float g_R [NELEM];
__device__ float g_X [NELEM];
__device__ float g_WT[6 * 1024 * 1024];
__device__ float2 g_stats[32768];
__device__ float g_gWo[1024];
__device__ float g_bWoBo[1024];
__device__ float g_bck[1024];
__device__ float g_bcq[1024];
__device__ float g_zero[1024];

// ---------------- helpers ----------------
__device__ __forceinline__ unsigned f2tf32(float f) {
    unsigned u;
    asm("cvt.rna.tf32.f32 %0, %1;" : "=r"(u) : "f"(f));
    return u;
}
__device__ __forceinline__ float rnd32(float f) { return __uint_as_float(f2tf32(f)); }

__device__ __forceinline__ uint32_t smem_u32(const void* p) {
    uint32_t a;
    asm("{ .reg .u64 t; cvta.to.shared.u64 t, %1; cvt.u32.u64 %0, t; }" : "=r"(a) : "l"(p));
    return a;
}
__device__ __forceinline__ void cp16(uint32_t dst, const void* src) {
    asm volatile("cp.async.cg.shared.global [%0], [%1], 16;\n" :: "r"(dst), "l"(src) : "memory");
}
__device__ __forceinline__ void cp_commit() {
    asm volatile("cp.async.commit_group;\n" ::: "memory");
}
template <int N> __device__ __forceinline__ void cp_wait() {
    asm volatile("cp.async.wait_group %0;\n" :: "n"(N) : "memory");
}
__device__ __forceinline__ void ldmx4(uint32_t& r0, uint32_t& r1, uint32_t& r2, uint32_t& r3,
                                      uint32_t addr) {
    asm volatile("ldmatrix.sync.aligned.m8n8.x4.shared.b16 {%0,%1,%2,%3}, [%4];"
                 : "=r"(r0), "=r"(r1), "=r"(r2), "=r"(r3) : "r"(addr));
}
__device__ __forceinline__ void mma_tf32(float c[4],
    uint32_t a0, uint32_t a1, uint32_t a2, uint32_t a3, uint32_t b0, uint32_t b1)
{
    asm volatile(
        "mma.sync.aligned.m16n8k8.row.col.f32.tf32.tf32.f32 "
        "{%0,%1,%2,%3}, {%4,%5,%6,%7}, {%8,%9}, {%0,%1,%2,%3};\n"
        : "+f"(c[0]), "+f"(c[1]), "+f"(c[2]), "+f"(c[3])
        : "r"(a0), "r"(a1), "r"(a2), "r"(a3), "r"(b0), "r"(b1));
}

struct GArgs {
    const float* A[3];
    const float* W[3];
    const float* b[3];
    float*       C[3];
    int epi[3];               // 0: +bias  1: tanh(+bias)*ps  3: LN-affine+residual
    int rnd[3];               // tf32-round the result
    const float* ps;          // epi1
    const float* resid;       // epi3: x
    const float2* stats;      // epi3: (rstd, mu*rstd)
    const float* gWo;         // epi3
};

// ---------------- GEMM (z-batched, runtime epilogue) ----------------
// C[z][M,1024] = A[z] @ W[z]^T.  Operands pre-rounded to tf32.
// W is [N rows, K cols]. 256 threads, warp tile 32x64, 3-stage cp.async.
__global__ void __launch_bounds__(256, 2)
gemm_rt(const GArgs args)
{
    extern __shared__ char smem[];
    const uint32_t tileBase = smem_u32(smem);

    const int z = blockIdx.z;
    const float* A    = args.A[z];
    const float* WT   = args.W[z];
    const float* bias = args.b[z];
    float*       C    = args.C[z];
    const int    epi  = args.epi[z];
    const int    rnd  = args.rnd[z];

    const int tid  = threadIdx.x;
    const int wid  = tid >> 5;
    const int lane = tid & 31;
    const int wm   = wid >> 1;
    const int wn   = wid & 1;
    const int g    = lane >> 2;
    const int tg   = lane & 3;

    const long bm0 = (long)blockIdx.y * MT;
    const int  bn0 = blockIdx.x * NT;

    const float* Abase = A  + bm0 * K_DIM;
    const float* Bbase = WT + (long)bn0 * K_DIM;

    const uint32_t rsw   = lane & 7;
    const uint32_t aoff0 = (uint32_t)((wm * 32 + ((lane >> 3) & 1) * 8 + (lane & 7)) * 128);
    const uint32_t hbitA = (lane >> 4) & 1;
    const uint32_t boff0 = (uint32_t)((wn * 64 + ((lane >> 4) & 1) * 8 + (lane & 7)) * 128) + 16384u;
    const uint32_t hbitB = (lane >> 3) & 1;

    auto fill = [&](int s) {
        const uint32_t buf = tileBase + (uint32_t)(s % STAGES) * STAGE_BYTES;
        const int k0 = s * KT;
        #pragma unroll
        for (int i = 0; i < 4; i++) {
            int o = tid + 256 * i;
            int row = o >> 3, c = o & 7;
            cp16(buf + (uint32_t)(row * 128 + ((c ^ (row & 7)) << 4)),
                 Abase + row * K_DIM + k0 + c * 4);
        }
        #pragma unroll
        for (int i = 0; i < 4; i++) {
            int o = tid + 256 * i;
            int row = o >> 3, c = o & 7;
            cp16(buf + 16384u + (uint32_t)(row * 128 + ((c ^ (row & 7)) << 4)),
                 Bbase + row * K_DIM + k0 + c * 4);
        }
        cp_commit();
    };

    float acc[2][8][4];
    #pragma unroll
    for (int i = 0; i < 2; i++)
        #pragma unroll
        for (int j = 0; j < 8; j++)
            #pragma unroll
            for (int k = 0; k < 4; k++)
                acc[i][j][k] = 0.f;

    fill(0);
    fill(1);

    #pragma unroll 1
    for (int kt = 0; kt < 32; kt++) {
        if (kt < 31) cp_wait<1>(); else cp_wait<0>();
        __syncthreads();
        if (kt < 30) fill(kt + 2);

        const uint32_t sbase = tileBase + (uint32_t)(kt % STAGES) * STAGE_BYTES;
        #pragma unroll
        for (int kk = 0; kk < 4; kk++) {
            uint32_t af[2][4], bf[8][2];
            const uint32_t cA = ((uint32_t)(kk * 2) + hbitA) ^ rsw;
            const uint32_t cB = ((uint32_t)(kk * 2) + hbitB) ^ rsw;
            ldmx4(af[0][0], af[0][1], af[0][2], af[0][3], sbase + aoff0 + (cA << 4));
            ldmx4(af[1][0], af[1][1], af[1][2], af[1][3], sbase + aoff0 + 2048u + (cA << 4));
            #pragma unroll
            for (int q = 0; q < 4; q++)
                ldmx4(bf[2 * q][0], bf[2 * q][1], bf[2 * q + 1][0], bf[2 * q + 1][1],
                      sbase + boff0 + (uint32_t)(q * 2048) + (cB << 4));
            #pragma unroll
            for (int im = 0; im < 2; im++)
                #pragma unroll
                for (int in = 0; in < 8; in++)
                    mma_tf32(acc[im][in],
                             af[im][0], af[im][1], af[im][2], af[im][3],
                             bf[in][0], bf[in][1]);
        }
    }

    // Epilogue (runtime-selected, out of the hot loop)
    #pragma unroll
    for (int im = 0; im < 2; im++) {
        #pragma unroll
        for (int in = 0; in < 8; in++) {
            const int col = bn0 + wn * 64 + in * 8 + 2 * tg;
            const float b0 = __ldg(bias + col);
            const float b1 = __ldg(bias + col + 1);
            #pragma unroll
            for (int h = 0; h < 2; h++) {
                const long row = bm0 + wm * 32 + im * 16 + g + h * 8;
                float v0, v1;
                if (epi == 3) {
                    const float2 st = __ldg(args.stats + row);
                    v0 = st.x * acc[im][in][2 * h + 0] - st.y * __ldg(args.gWo + col) + b0
                         + args.resid[row * N_DIM + col];
                    v1 = st.x * acc[im][in][2 * h + 1] - st.y * __ldg(args.gWo + col + 1) + b1
                         + args.resid[row * N_DIM + col + 1];
                } else {
                    v0 = acc[im][in][2 * h + 0] + b0;
                    v1 = acc[im][in][2 * h + 1] + b1;
                    if (epi == 1) {
                        v0 = tanhf(v0) * __ldg(args.ps + col);
                        v1 = tanhf(v1) * __ldg(args.ps + col + 1);
                    }
                    if (rnd) { v0 = rnd32(v0); v1 = rnd32(v1); }
                }
                *(float2*)(C + row * N_DIM + col) = make_float2(v0, v1);
            }
        }
    }
}

// ---------------- prep kernels ----------------
struct W4 { const float* w[4]; };

__global__ void __launch_bounds__(256)
wtrans_all_k(const W4 ws, float* __restrict__ WT)
{
    __shared__ float t[32][33];
    static const int slot[4] = {0, 1, 2, 5};
    const float* W = ws.w[blockIdx.z];
    float* D = WT + (long)slot[blockIdx.z] * 1048576;
    int bx = blockIdx.x * 32, by = blockIdx.y * 32;
    #pragma unroll
    for (int i = threadIdx.y; i < 32; i += 8)
        t[i][threadIdx.x] = W[(by + i) * 1024 + bx + threadIdx.x];
    __syncthreads();
    #pragma unroll
    for (int i = threadIdx.y; i < 32; i += 8)
        D[(bx + i) * 1024 + by + threadIdx.x] = rnd32(t[threadIdx.x][i]);
}

__global__ void __launch_bounds__(256)
round_x_k(const float* __restrict__ x, float* __restrict__ o)
{
    long i = ((long)blockIdx.x * 256 + threadIdx.x) * 4;
    float4 v = *(const float4*)(x + i);
    v.x = rnd32(v.x); v.y = rnd32(v.y); v.z = rnd32(v.z); v.w = rnd32(v.w);
    *(float4*)(o + i) = v;
}

__global__ void __launch_bounds__(256)
round_w_k(const float* __restrict__ w0, const float* __restrict__ w1,
          float* __restrict__ o0, float* __restrict__ o1)
{
    const float* s = blockIdx.y ? w1 : w0;
    float* d = blockIdx.y ? o1 : o0;
    long i = ((long)blockIdx.x * 256 + threadIdx.x) * 4;
    float4 v = *(const float4*)(s + i);
    v.x = rnd32(v.x); v.y = rnd32(v.y); v.z = rnd32(v.z); v.w = rnd32(v.w);
    *(float4*)(d + i) = v;
}

// GEMVs from transposed (tf32-rounded) weights: one warp per output column.
// gWo = g@Wo ; bWoBo = b@Wo + bo ; bck = bk@Wkp + bkp ; bcq = bq@Wqp + bqp
__global__ void __launch_bounds__(256)
gemv_prep_k(const float* __restrict__ WoT, const float* __restrict__ WkpT,
            const float* __restrict__ WqpT,
            const float* __restrict__ g, const float* __restrict__ b,
            const float* __restrict__ bo,
            const float* __restrict__ bk, const float* __restrict__ bkp,
            const float* __restrict__ bq, const float* __restrict__ bqp,
            float* __restrict__ gWo, float* __restrict__ bWoBo,
            float* __restrict__ bck, float* __restrict__ bcq)
{
    const int lane = threadIdx.x & 31;
    const int col  = blockIdx.x * 8 + (threadIdx.x >> 5);
    const float* wo  = WoT  + (long)col * 1024;
    const float* wkp = WkpT + (long)col * 1024;
    const float* wqp = WqpT + (long)col * 1024;
    float a1 = 0.f, a2 = 0.f, a3 = 0.f, a4 = 0.f;
    #pragma unroll 8
    for (int d = lane; d < 1024; d += 32) {
        float w = wo[d];
        a1 = fmaf(__ldg(g + d), w, a1);
        a2 = fmaf(__ldg(b + d), w, a2);
        a3 = fmaf(__ldg(bk + d), wkp[d], a3);
        a4 = fmaf(__ldg(bq + d), wqp[d], a4);
    }
    #pragma unroll
    for (int o = 16; o; o >>= 1) {
        a1 += __shfl_xor_sync(0xffffffffu, a1, o);
        a2 += __shfl_xor_sync(0xffffffffu, a2, o);
        a3 += __shfl_xor_sync(0xffffffffu, a3, o);
        a4 += __shfl_xor_sync(0xffffffffu, a4, o);
    }
    if (lane == 0) {
        gWo[col]   = a1;
        bWoBo[col] = a2 + bo[col];
        bck[col]   = a3 + bkp[col];
        bcq[col]   = a4 + bqp[col];
    }
}

// ---------------- bind + chunk scan + row stats + gamma fold ----------------
__global__ void __launch_bounds__(256)
bind_scan_k(const float* __restrict__ V, const float* __restrict__ KP,
            const float* __restrict__ QP, const float* __restrict__ lng,
            float* __restrict__ R, float2* __restrict__ stats)
{
    __shared__ float2 part[64][8];
    const float inv = 0.03125f;  // 1/sqrt(1024)
    const int tid = threadIdx.x;
    const int lane = tid & 31, w = tid >> 5;
    long idx = (long)blockIdx.x * 64 * 1024 + tid * 4;
    float4 mr = make_float4(0.f, 0.f, 0.f, 0.f);
    float4 mi = make_float4(0.f, 0.f, 0.f, 0.f);
    const float4 gv = *(const float4*)(lng + tid * 4);

    #pragma unroll 4
    for (int s = 0; s < 64; s++, idx += 1024) {
        float4 v  = *(const float4*)(V + idx);
        float4 kp = *(const float4*)(KP + idx);
        float4 qp = *(const float4*)(QP + idx);
        float4 out;
        float sk, ck, sq, cq;
        __sincosf(kp.x, &sk, &ck);
        mr.x = fmaf(v.x, ck, mr.x); mi.x = fmaf(v.x, sk, mi.x);
        __sincosf(qp.x, &sq, &cq);
        out.x = (mr.x * cq + mi.x * sq) * inv;
        __sincosf(kp.y, &sk, &ck);
        mr.y = fmaf(v.y, ck, mr.y); mi.y = fmaf(v.y, sk, mi.y);
        __sincosf(qp.y, &sq, &cq);
        out.y = (mr.y * cq + mi.y * sq) * inv;
        __sincosf(kp.z, &sk, &ck);
        mr.z = fmaf(v.z, ck, mr.z); mi.z = fmaf(v.z, sk, mi.z);
        __sincosf(qp.z, &sq, &cq);
        out.z = (mr.z * cq + mi.z * sq) * inv;
        __sincosf(kp.w, &sk, &ck);
        mr.w = fmaf(v.w, ck, mr.w); mi.w = fmaf(v.w, sk, mi.w);
        __sincosf(qp.w, &sq, &cq);
        out.w = (mr.w * cq + mi.w * sq) * inv;

        float rs = out.x + out.y + out.z + out.w;
        float rq = out.x * out.x + out.y * out.y + out.z * out.z + out.w * out.w;
        #pragma unroll
        for (int o = 16; o; o >>= 1) {
            rs += __shfl_xor_sync(0xffffffffu, rs, o);
            rq += __shfl_xor_sync(0xffffffffu, rq, o);
        }
        if (lane == 0) part[s][w] = make_float2(rs, rq);

        out.x = rnd32(out.x * gv.x);
        out.y = rnd32(out.y * gv.y);
        out.z = rnd32(out.z * gv.z);
        out.w = rnd32(out.w * gv.w);
        *(float4*)(R + idx) = out;
    }
    __syncthreads();
    if (tid < 64) {
        float S = 0.f, Q = 0.f;
        #pragma unroll
        for (int i = 0; i < 8; i++) { S += part[tid][i].x; Q += part[tid][i].y; }
        float mu = S * (1.f / 1024.f);
        float var = Q * (1.f / 1024.f) - mu * mu;
        float rstd = rsqrtf(var + 1e-5f);
        stats[blockIdx.x * 64 + tid] = make_float2(rstd, mu * rstd);
    }
}

extern "C" void kernel_launch(void* const* d_in, const int* in_sizes, int n_in,
                              void* d_out, int out_size)
{
    const float* x   = (const float*)d_in[0];
    const float* Wk  = (const float*)d_in[1];
    const float* bk  = (const float*)d_in[2];
    const float* Wv  = (const float*)d_in[3];
    const float* bv  = (const float*)d_in[4];
    const float* Wq  = (const float*)d_in[5];
    const float* bq  = (const float*)d_in[6];
    const float* Wkp = (const float*)d_in[7];
    const float* bkp = (const float*)d_in[8];
    const float* Wqp = (const float*)d_in[9];
    const float* bqp = (const float*)d_in[10];
    const float* ps  = (const float*)d_in[11];
    const float* lng = (const float*)d_in[12];
    const float* lnb = (const float*)d_in[13];
    const float* Wo  = (const float*)d_in[14];
    const float* bo  = (const float*)d_in[15];
    float* out = (float*)d_out;

    const int M = in_sizes[0] / 1024;  // 32768

    float *pV, *pKP, *pQP, *pR, *pX, *pWT, *pWkR, *pWqR;
    float *pgWo, *pbWoBo, *pbck, *pbcq, *pzero;
    float2* pStats;
    cudaGetSymbolAddress((void**)&pV,   g_V);
    cudaGetSymbolAddress((void**)&pKP,  g_KP);
    cudaGetSymbolAddress((void**)&pQP,  g_QP);
    cudaGetSymbolAddress((void**)&pR,   g_R);
    cudaGetSymbolAddress((void**)&pX,   g_X);
    cudaGetSymbolAddress((void**)&pWT,  g_WT);
    cudaGetSymbolAddress((void**)&pWkR, g_WkR);
    cudaGetSymbolAddress((void**)&pWqR, g_WqR);
    cudaGetSymbolAddress((void**)&pStats, g_stats);
    cudaGetSymbolAddress((void**)&pgWo, g_gWo);
    cudaGetSymbolAddress((void**)&pbWoBo, g_bWoBo);
    cudaGetSymbolAddress((void**)&pbck, g_bck);
    cudaGetSymbolAddress((void**)&pbcq, g_bcq);
    cudaGetSymbolAddress((void**)&pzero, g_zero);

    cudaFuncSetAttribute(gemm_rt, cudaFuncAttributeMaxDynamicSharedMemorySize, SMEM_TOTAL);

    // prep: transpose+round (Wv, Wkp, Wqp, Wo); round Wk, Wq; round x; biases
    W4 ws;
    ws.w[0] = Wv; ws.w[1] = Wkp; ws.w[2] = Wqp; ws.w[3] = Wo;
    wtrans_all_k<<<dim3(32, 32, 4), dim3(32, 8)>>>(ws, pWT);
    round_w_k<<<dim3(1024, 2), 256>>>(Wk, Wq, pWkR, pWqR);
    round_x_k<<<NELEM / 1024, 256>>>(x, pX);
    gemv_prep_k<<<128, 256>>>(pWT + 5 * 1048576, pWT + 1 * 1048576, pWT + 2 * 1048576,
                              lng, lnb, bo, bk, bkp, bq, bqp,
                              pgWo, pbWoBo, pbck, pbcq);

    GArgs a{};
    a.ps = ps; a.resid = x; a.stats = pStats; a.gWo = pgWo;

    // Weight composition: WckT = WkpT x WkR -> slot3 ; WcqT = WqpT x WqR -> slot4
    a.A[0] = pWT + 1 * 1048576; a.A[1] = pWT + 2 * 1048576; a.A[2] = a.A[1];
    a.W[0] = pWkR;              a.W[1] = pWqR;              a.W[2] = a.W[1];
    a.b[0] = pzero; a.b[1] = pzero; a.b[2] = pzero;
    a.C[0] = pWT + 3 * 1048576; a.C[1] = pWT + 4 * 1048576; a.C[2] = a.C[1];
    a.epi[0] = 0; a.epi[1] = 0; a.epi[2] = 0;
    a.rnd[0] = 1; a.rnd[1] = 1; a.rnd[2] = 1;
    gemm_rt<<<dim3(8, 8, 2), 256, SMEM_TOTAL>>>(a);

    // Big batch: V = X@WvT+bv ; KP = tanh(X@WckT+bck)*ps ; QP = tanh(X@WcqT+bcq)*ps
    a.A[0] = pX; a.A[1] = pX; a.A[2] = pX;
    a.W[0] = pWT + 0 * 1048576; a.W[1] = pWT + 3 * 1048576; a.W[2] = pWT + 4 * 1048576;
    a.b[0] = bv; a.b[1] = pbck; a.b[2] = pbcq;
    a.C[0] = pV; a.C[1] = pKP; a.C[2] = pQP;
    a.epi[0] = 0; a.epi[1] = 1; a.epi[2] = 1;
    a.rnd[0] = 0; a.rnd[1] = 0; a.rnd[2] = 0;
    gemm_rt<<<dim3(N_DIM / NT, M / MT, 3), 256, SMEM_TOTAL>>>(a);

    bind_scan_k<<<M / 64, 256>>>(pV, pKP, pQP, lng, pR, pStats);

    // Output GEMM with fused LayerNorm-affine + residual
    a.A[0] = pR; a.A[1] = pR; a.A[2] = pR;
    a.W[0] = pWT + 5 * 1048576; a.W[1] = a.W[0]; a.W[2] = a.W[0];
    a.b[0] = pbWoBo; a.b[1] = pbWoBo; a.b[2] = pbWoBo;
    a.C[0] = out; a.C[1] = out; a.C[2] = out;
    a.epi[0] = 3; a.epi[1] = 3; a.epi[2] = 3;
    a.rnd[0] = 0; a.rnd[1] = 0; a.rnd[2] = 0;
    gemm_rt<<<dim3(N_DIM / NT, M / MT, 1), 256, SMEM_TOTAL>>>(a);
}

// round 9
// speedup vs baseline: 2.4052x; 1.6793x over previous
#include <cuda_runtime.h>
#include <cuda_fp16.h>
#include <cstdint>
#include <math.h>

#define N_DIM 1024
#define K_DIM 1024
#define NELEM 33554432  // 4*8192*1024

#define MT 128
#define NT 128
#define KT 64
#define KITERS 16
#define STAGES 3
#define STAGE_BYTES 32768                 // A 16KB + B 16KB (fp16)
#define SMEM_TOTAL (STAGES * STAGE_BYTES) // 96KB

// Scratch (device globals; zero-initialized)
__device__ __half g_WkR[1048576];
__device__ __half g_WqR[1048576];
__device__ float  g_V [NELEM];
__device__ float  g_KP[NELEM];
__device__ float  g_QP[NELEM];
__device__ __half g_R [NELEM];
__device__ __half g_X [NELEM];
__device__ __half g_WT[6 * 1024 * 1024];
__device__ float2 g_stats[32768];
__device__ float  g_gWo[1024];
__device__ float  g_bWoBo[1024];
__device__ float  g_bck[1024];
__device__ float  g_bcq[1024];
__device__ float  g_zero[1024];

// ---------------- helpers ----------------
__device__ __forceinline__ uint32_t smem_u32(const void* p) {
    uint32_t a;
    asm("{ .reg .u64 t; cvta.to.shared.u64 t, %1; cvt.u32.u64 %0, t; }" : "=r"(a) : "l"(p));
    return a;
}
__device__ __forceinline__ void cp16(uint32_t dst, const void* src) {
    asm volatile("cp.async.cg.shared.global [%0], [%1], 16;\n" :: "r"(dst), "l"(src) : "memory");
}
__device__ __forceinline__ void cp_commit() {
    asm volatile("cp.async.commit_group;\n" ::: "memory");
}
template <int N> __device__ __forceinline__ void cp_wait() {
    asm volatile("cp.async.wait_group %0;\n" :: "n"(N) : "memory");
}
__device__ __forceinline__ void ldmx4(uint32_t& r0, uint32_t& r1, uint32_t& r2, uint32_t& r3,
                                      uint32_t addr) {
    asm volatile("ldmatrix.sync.aligned.m8n8.x4.shared.b16 {%0,%1,%2,%3}, [%4];"
                 : "=r"(r0), "=r"(r1), "=r"(r2), "=r"(r3) : "r"(addr));
}
// fp16 MMA, f32 accumulate: D(16x8) += A(16x16) x B(16x8)
__device__ __forceinline__ void mma_f16(float c[4],
    uint32_t a0, uint32_t a1, uint32_t a2, uint32_t a3, uint32_t b0, uint32_t b1)
{
    asm volatile(
        "mma.sync.aligned.m16n8k16.row.col.f32.f16.f16.f32 "
        "{%0,%1,%2,%3}, {%4,%5,%6,%7}, {%8,%9}, {%0,%1,%2,%3};\n"
        : "+f"(c[0]), "+f"(c[1]), "+f"(c[2]), "+f"(c[3])
        : "r"(a0), "r"(a1), "r"(a2), "r"(a3), "r"(b0), "r"(b1));
}

struct GArgs {
    const __half* A[3];
    const __half* W[3];
    const float*  b[3];
    void*         C[3];
    int epi[3];               // 0: +bias  1: tanh(+bias)*ps  3: LN-affine+residual
    int oh[3];                // 1: store output as fp16 (becomes a W/A of a later GEMM)
    const float* ps;          // epi1
    const float* resid;       // epi3: x
    const float2* stats;      // epi3: (rstd, mu*rstd)
    const float* gWo;         // epi3
};

// ---------------- GEMM (fp16 in, f32 acc, z-batched, runtime epilogue) ----------------
// C[z][M,1024] = A[z] @ W[z]^T.  W is [N rows, K cols], both fp16.
// 256 threads (8 warps), warp tile 32x64, 3-stage cp.async, XOR-swizzled ldmatrix.
__global__ void __launch_bounds__(256, 2)
gemm_rt(const GArgs args)
{
    extern __shared__ char smem[];
    const uint32_t tileBase = smem_u32(smem);

    const int z = blockIdx.z;
    const __half* A    = args.A[z];
    const __half* WT   = args.W[z];
    const float*  bias = args.b[z];
    void*         C    = args.C[z];
    const int     epi  = args.epi[z];
    const int     oh   = args.oh[z];

    const int tid  = threadIdx.x;
    const int wid  = tid >> 5;
    const int lane = tid & 31;
    const int wm   = wid >> 1;
    const int wn   = wid & 1;
    const int g    = lane >> 2;
    const int tg   = lane & 3;

    const long bm0 = (long)blockIdx.y * MT;
    const int  bn0 = blockIdx.x * NT;

    const __half* Abase = A  + bm0 * K_DIM;
    const __half* Bbase = WT + (long)bn0 * K_DIM;

    // rows 128B apart (64 fp16), 8 chunks of 16B, XOR-swizzled by row&7
    const uint32_t rsw   = lane & 7;
    const uint32_t aoff0 = (uint32_t)((wm * 32 + ((lane >> 3) & 1) * 8 + (lane & 7)) * 128);
    const uint32_t hbitA = (lane >> 4) & 1;
    const uint32_t boff0 = (uint32_t)((wn * 64 + ((lane >> 4) & 1) * 8 + (lane & 7)) * 128) + 16384u;
    const uint32_t hbitB = (lane >> 3) & 1;

    auto fill = [&](int s) {
        const uint32_t buf = tileBase + (uint32_t)(s % STAGES) * STAGE_BYTES;
        const int k0 = s * KT;
        #pragma unroll
        for (int i = 0; i < 4; i++) {          // A: 128 rows x 8 chunks (16B = 8 fp16)
            int o = tid + 256 * i;
            int row = o >> 3, c = o & 7;
            cp16(buf + (uint32_t)(row * 128 + ((c ^ (row & 7)) << 4)),
                 Abase + (long)row * K_DIM + k0 + c * 8);
        }
        #pragma unroll
        for (int i = 0; i < 4; i++) {          // B
            int o = tid + 256 * i;
            int row = o >> 3, c = o & 7;
            cp16(buf + 16384u + (uint32_t)(row * 128 + ((c ^ (row & 7)) << 4)),
                 Bbase + (long)row * K_DIM + k0 + c * 8);
        }
        cp_commit();
    };

    float acc[2][8][4];
    #pragma unroll
    for (int i = 0; i < 2; i++)
        #pragma unroll
        for (int j = 0; j < 8; j++)
            #pragma unroll
            for (int k = 0; k < 4; k++)
                acc[i][j][k] = 0.f;

    fill(0);
    fill(1);

    #pragma unroll 1
    for (int kt = 0; kt < KITERS; kt++) {
        if (kt < KITERS - 1) cp_wait<1>(); else cp_wait<0>();
        __syncthreads();
        if (kt < KITERS - 2) fill(kt + 2);

        const uint32_t sbase = tileBase + (uint32_t)(kt % STAGES) * STAGE_BYTES;
        #pragma unroll
        for (int kk = 0; kk < 4; kk++) {       // K=16 per kk
            uint32_t af[2][4], bf[8][2];
            const uint32_t cA = ((uint32_t)(kk * 2) + hbitA) ^ rsw;
            const uint32_t cB = ((uint32_t)(kk * 2) + hbitB) ^ rsw;
            ldmx4(af[0][0], af[0][1], af[0][2], af[0][3], sbase + aoff0 + (cA << 4));
            ldmx4(af[1][0], af[1][1], af[1][2], af[1][3], sbase + aoff0 + 2048u + (cA << 4));
            #pragma unroll
            for (int q = 0; q < 4; q++)
                ldmx4(bf[2 * q][0], bf[2 * q][1], bf[2 * q + 1][0], bf[2 * q + 1][1],
                      sbase + boff0 + (uint32_t)(q * 2048) + (cB << 4));
            #pragma unroll
            for (int im = 0; im < 2; im++)
                #pragma unroll
                for (int in = 0; in < 8; in++)
                    mma_f16(acc[im][in],
                            af[im][0], af[im][1], af[im][2], af[im][3],
                            bf[in][0], bf[in][1]);
        }
    }

    // Epilogue
    #pragma unroll
    for (int im = 0; im < 2; im++) {
        #pragma unroll
        for (int in = 0; in < 8; in++) {
            const int col = bn0 + wn * 64 + in * 8 + 2 * tg;
            const float b0 = __ldg(bias + col);
            const float b1 = __ldg(bias + col + 1);
            #pragma unroll
            for (int h = 0; h < 2; h++) {
                const long row = bm0 + wm * 32 + im * 16 + g + h * 8;
                float v0, v1;
                if (epi == 3) {
                    const float2 st = __ldg(args.stats + row);
                    v0 = st.x * acc[im][in][2 * h + 0] - st.y * __ldg(args.gWo + col) + b0
                         + args.resid[row * N_DIM + col];
                    v1 = st.x * acc[im][in][2 * h + 1] - st.y * __ldg(args.gWo + col + 1) + b1
                         + args.resid[row * N_DIM + col + 1];
                } else {
                    v0 = acc[im][in][2 * h + 0] + b0;
                    v1 = acc[im][in][2 * h + 1] + b1;
                    if (epi == 1) {
                        v0 = tanhf(v0) * __ldg(args.ps + col);
                        v1 = tanhf(v1) * __ldg(args.ps + col + 1);
                    }
                }
                if (oh) {
                    *(__half2*)((__half*)C + row * N_DIM + col) = __floats2half2_rn(v0, v1);
                } else {
                    *(float2*)((float*)C + row * N_DIM + col) = make_float2(v0, v1);
                }
            }
        }
    }
}

// ---------------- prep kernels ----------------
struct W4 { const float* w[4]; };

// transpose + convert to fp16 -> WT slots {0,1,2,5}
__global__ void __launch_bounds__(256)
wtrans_all_k(const W4 ws, __half* __restrict__ WT)
{
    __shared__ float t[32][33];
    static const int slot[4] = {0, 1, 2, 5};
    const float* W = ws.w[blockIdx.z];
    __half* D = WT + (long)slot[blockIdx.z] * 1048576;
    int bx = blockIdx.x * 32, by = blockIdx.y * 32;
    #pragma unroll
    for (int i = threadIdx.y; i < 32; i += 8)
        t[i][threadIdx.x] = W[(by + i) * 1024 + bx + threadIdx.x];
    __syncthreads();
    #pragma unroll
    for (int i = threadIdx.y; i < 32; i += 8)
        D[(bx + i) * 1024 + by + threadIdx.x] = __float2half_rn(t[threadIdx.x][i]);
}

// f32 -> fp16 (8 elems/thread)
__global__ void __launch_bounds__(256)
cvt_h_k(const float* __restrict__ s, __half* __restrict__ d)
{
    long i = ((long)blockIdx.x * 256 + threadIdx.x) * 8;
    float4 v0 = *(const float4*)(s + i);
    float4 v1 = *(const float4*)(s + i + 4);
    __half2 h[4];
    h[0] = __floats2half2_rn(v0.x, v0.y);
    h[1] = __floats2half2_rn(v0.z, v0.w);
    h[2] = __floats2half2_rn(v1.x, v1.y);
    h[3] = __floats2half2_rn(v1.z, v1.w);
    *(uint4*)(d + i) = *(uint4*)h;
}

// GEMVs from fp16 transposed weights: one warp per output column.
__global__ void __launch_bounds__(256)
gemv_prep_k(const __half* __restrict__ WoT, const __half* __restrict__ WkpT,
            const __half* __restrict__ WqpT,
            const float* __restrict__ g, const float* __restrict__ b,
            const float* __restrict__ bo,
            const float* __restrict__ bk, const float* __restrict__ bkp,
            const float* __restrict__ bq, const float* __restrict__ bqp,
            float* __restrict__ gWo, float* __restrict__ bWoBo,
            float* __restrict__ bck, float* __restrict__ bcq)
{
    const int lane = threadIdx.x & 31;
    const int col  = blockIdx.x * 8 + (threadIdx.x >> 5);
    const __half* wo  = WoT  + (long)col * 1024;
    const __half* wkp = WkpT + (long)col * 1024;
    const __half* wqp = WqpT + (long)col * 1024;
    float a1 = 0.f, a2 = 0.f, a3 = 0.f, a4 = 0.f;
    #pragma unroll 8
    for (int d = lane; d < 1024; d += 32) {
        float w = __half2float(wo[d]);
        a1 = fmaf(__ldg(g + d), w, a1);
        a2 = fmaf(__ldg(b + d), w, a2);
        a3 = fmaf(__ldg(bk + d), __half2float(wkp[d]), a3);
        a4 = fmaf(__ldg(bq + d), __half2float(wqp[d]), a4);
    }
    #pragma unroll
    for (int o = 16; o; o >>= 1) {
        a1 += __shfl_xor_sync(0xffffffffu, a1, o);
        a2 += __shfl_xor_sync(0xffffffffu, a2, o);
        a3 += __shfl_xor_sync(0xffffffffu, a3, o);
        a4 += __shfl_xor_sync(0xffffffffu, a4, o);
    }
    if (lane == 0) {
        gWo[col]   = a1;
        bWoBo[col] = a2 + bo[col];
        bck[col]   = a3 + bkp[col];
        bcq[col]   = a4 + bqp[col];
    }
}

// ---------------- bind + chunk scan + row stats + gamma fold (R in fp16) ----------------
__global__ void __launch_bounds__(256)
bind_scan_k(const float* __restrict__ V, const float* __restrict__ KP,
            const float* __restrict__ QP, const float* __restrict__ lng,
            __half* __restrict__ R, float2* __restrict__ stats)
{
    __shared__ float2 part[64][8];
    const float inv = 0.03125f;  // 1/sqrt(1024)
    const int tid = threadIdx.x;
    const int lane = tid & 31, w = tid >> 5;
    long idx = (long)blockIdx.x * 64 * 1024 + tid * 4;
    float4 mr = make_float4(0.f, 0.f, 0.f, 0.f);
    float4 mi = make_float4(0.f, 0.f, 0.f, 0.f);
    const float4 gv = *(const float4*)(lng + tid * 4);

    #pragma unroll 4
    for (int s = 0; s < 64; s++, idx += 1024) {
        float4 v  = *(const float4*)(V + idx);
        float4 kp = *(const float4*)(KP + idx);
        float4 qp = *(const float4*)(QP + idx);
        float4 out;
        float sk, ck, sq, cq;
        __sincosf(kp.x, &sk, &ck);
        mr.x = fmaf(v.x, ck, mr.x); mi.x = fmaf(v.x, sk, mi.x);
        __sincosf(qp.x, &sq, &cq);
        out.x = (mr.x * cq + mi.x * sq) * inv;
        __sincosf(kp.y, &sk, &ck);
        mr.y = fmaf(v.y, ck, mr.y); mi.y = fmaf(v.y, sk, mi.y);
        __sincosf(qp.y, &sq, &cq);
        out.y = (mr.y * cq + mi.y * sq) * inv;
        __sincosf(kp.z, &sk, &ck);
        mr.z = fmaf(v.z, ck, mr.z); mi.z = fmaf(v.z, sk, mi.z);
        __sincosf(qp.z, &sq, &cq);
        out.z = (mr.z * cq + mi.z * sq) * inv;
        __sincosf(kp.w, &sk, &ck);
        mr.w = fmaf(v.w, ck, mr.w); mi.w = fmaf(v.w, sk, mi.w);
        __sincosf(qp.w, &sq, &cq);
        out.w = (mr.w * cq + mi.w * sq) * inv;

        float rs = out.x + out.y + out.z + out.w;
        float rq = out.x * out.x + out.y * out.y + out.z * out.z + out.w * out.w;
        #pragma unroll
        for (int o = 16; o; o >>= 1) {
            rs += __shfl_xor_sync(0xffffffffu, rs, o);
            rq += __shfl_xor_sync(0xffffffffu, rq, o);
        }
        if (lane == 0) part[s][w] = make_float2(rs, rq);

        __half2 h0 = __floats2half2_rn(out.x * gv.x, out.y * gv.y);
        __half2 h1 = __floats2half2_rn(out.z * gv.z, out.w * gv.w);
        uint2 pk = make_uint2(*(uint32_t*)&h0, *(uint32_t*)&h1);
        *(uint2*)(R + idx) = pk;
    }
    __syncthreads();
    if (tid < 64) {
        float S = 0.f, Q = 0.f;
        #pragma unroll
        for (int i = 0; i < 8; i++) { S += part[tid][i].x; Q += part[tid][i].y; }
        float mu = S * (1.f / 1024.f);
        float var = Q * (1.f / 1024.f) - mu * mu;
        float rstd = rsqrtf(var + 1e-5f);
        stats[blockIdx.x * 64 + tid] = make_float2(rstd, mu * rstd);
    }
}

extern "C" void kernel_launch(void* const* d_in, const int* in_sizes, int n_in,
                              void* d_out, int out_size)
{
    const float* x   = (const float*)d_in[0];
    const float* Wk  = (const float*)d_in[1];
    const float* bk  = (const float*)d_in[2];
    const float* Wv  = (const float*)d_in[3];
    const float* bv  = (const float*)d_in[4];
    const float* Wq  = (const float*)d_in[5];
    const float* bq  = (const float*)d_in[6];
    const float* Wkp = (const float*)d_in[7];
    const float* bkp = (const float*)d_in[8];
    const float* Wqp = (const float*)d_in[9];
    const float* bqp = (const float*)d_in[10];
    const float* ps  = (const float*)d_in[11];
    const float* lng = (const float*)d_in[12];
    const float* lnb = (const float*)d_in[13];
    const float* Wo  = (const float*)d_in[14];
    const float* bo  = (const float*)d_in[15];
    float* out = (float*)d_out;

    const int M = in_sizes[0] / 1024;  // 32768

    float *pV, *pKP, *pQP;
    __half *pR, *pX, *pWT, *pWkR, *pWqR;
    float *pgWo, *pbWoBo, *pbck, *pbcq, *pzero;
    float2* pStats;
    cudaGetSymbolAddress((void**)&pV,   g_V);
    cudaGetSymbolAddress((void**)&pKP,  g_KP);
    cudaGetSymbolAddress((void**)&pQP,  g_QP);
    cudaGetSymbolAddress((void**)&pR,   g_R);
    cudaGetSymbolAddress((void**)&pX,   g_X);
    cudaGetSymbolAddress((void**)&pWT,  g_WT);
    cudaGetSymbolAddress((void**)&pWkR, g_WkR);
    cudaGetSymbolAddress((void**)&pWqR, g_WqR);
    cudaGetSymbolAddress((void**)&pStats, g_stats);
    cudaGetSymbolAddress((void**)&pgWo, g_gWo);
    cudaGetSymbolAddress((void**)&pbWoBo, g_bWoBo);
    cudaGetSymbolAddress((void**)&pbck, g_bck);
    cudaGetSymbolAddress((void**)&pbcq, g_bcq);
    cudaGetSymbolAddress((void**)&pzero, g_zero);

    cudaFuncSetAttribute(gemm_rt, cudaFuncAttributeMaxDynamicSharedMemorySize, SMEM_TOTAL);

    // prep: transpose+cvt (Wv, Wkp, Wqp, Wo); cvt Wk, Wq, x; bias GEMVs
    W4 ws;
    ws.w[0] = Wv; ws.w[1] = Wkp; ws.w[2] = Wqp; ws.w[3] = Wo;
    wtrans_all_k<<<dim3(32, 32, 4), dim3(32, 8)>>>(ws, pWT);
    cvt_h_k<<<512, 256>>>(Wk, pWkR);
    cvt_h_k<<<512, 256>>>(Wq, pWqR);
    cvt_h_k<<<NELEM / 2048, 256>>>(x, pX);
    gemv_prep_k<<<128, 256>>>(pWT + 5 * 1048576, pWT + 1 * 1048576, pWT + 2 * 1048576,
                              lng, lnb, bo, bk, bkp, bq, bqp,
                              pgWo, pbWoBo, pbck, pbcq);

    GArgs a{};
    a.ps = ps; a.resid = x; a.stats = pStats; a.gWo = pgWo;

    // Weight composition: WckT = WkpT x WkR -> slot3 ; WcqT = WqpT x WqR -> slot4 (fp16 out)
    a.A[0] = pWT + 1 * 1048576; a.A[1] = pWT + 2 * 1048576; a.A[2] = a.A[1];
    a.W[0] = pWkR;              a.W[1] = pWqR;              a.W[2] = a.W[1];
    a.b[0] = pzero; a.b[1] = pzero; a.b[2] = pzero;
    a.C[0] = pWT + 3 * 1048576; a.C[1] = pWT + 4 * 1048576; a.C[2] = a.C[1];
    a.epi[0] = 0; a.epi[1] = 0; a.epi[2] = 0;
    a.oh[0] = 1; a.oh[1] = 1; a.oh[2] = 1;
    gemm_rt<<<dim3(8, 8, 2), 256, SMEM_TOTAL>>>(a);

    // Big batch: V = X@WvT+bv ; KP = tanh(X@WckT+bck)*ps ; QP = tanh(X@WcqT+bcq)*ps
    a.A[0] = pX; a.A[1] = pX; a.A[2] = pX;
    a.W[0] = pWT + 0 * 1048576; a.W[1] = pWT + 3 * 1048576; a.W[2] = pWT + 4 * 1048576;
    a.b[0] = bv; a.b[1] = pbck; a.b[2] = pbcq;
    a.C[0] = pV; a.C[1] = pKP; a.C[2] = pQP;
    a.epi[0] = 0; a.epi[1] = 1; a.epi[2] = 1;
    a.oh[0] = 0; a.oh[1] = 0; a.oh[2] = 0;
    gemm_rt<<<dim3(N_DIM / NT, M / MT, 3), 256, SMEM_TOTAL>>>(a);

    bind_scan_k<<<M / 64, 256>>>(pV, pKP, pQP, lng, pR, pStats);

    // Output GEMM with fused LayerNorm-affine + residual
    a.A[0] = pR; a.A[1] = pR; a.A[2] = pR;
    a.W[0] = pWT + 5 * 1048576; a.W[1] = a.W[0]; a.W[2] = a.W[0];
    a.b[0] = pbWoBo; a.b[1] = pbWoBo; a.b[2] = pbWoBo;
    a.C[0] = out; a.C[1] = out; a.C[2] = out;
    a.epi[0] = 3; a.epi[1] = 3; a.epi[2] = 3;
    a.oh[0] = 0; a.oh[1] = 0; a.oh[2] = 0;
    gemm_rt<<<dim3(N_DIM / NT, M / MT, 1), 256, SMEM_TOTAL>>>(a);
}

// round 10
// speedup vs baseline: 2.4066x; 1.0006x over previous
#include <cuda_runtime.h>
#include <cuda_fp16.h>
#include <cstdint>
#include <math.h>

#define N_DIM 1024
#define K_DIM 1024
#define NELEM 33554432  // 4*8192*1024

#define MT 128
#define NT 128
#define KT 64
#define KITERS 16
#define STAGES 3
#define STAGE_BYTES 32768                 // A 16KB + B 16KB (fp16)
#define SMEM_TOTAL (STAGES * STAGE_BYTES) // 96KB

// Scratch (device globals; zero-initialized)
__device__ __half g_WkR[1048576];
__device__ __half g_WqR[1048576];
__device__ __half g_Vh[NELEM];
__device__ float  g_KP[NELEM];
__device__ float  g_QP[NELEM];
__device__ __half g_R [NELEM];
__device__ __half g_X [NELEM];
__device__ __half g_WT[6 * 1024 * 1024];
__device__ float2 g_stats[32768];
__device__ float  g_gWo[1024];
__device__ float  g_bWoBo[1024];
__device__ float  g_bck[1024];
__device__ float  g_bcq[1024];
__device__ float  g_zero[1024];

// ---------------- helpers ----------------
__device__ __forceinline__ uint32_t smem_u32(const void* p) {
    uint32_t a;
    asm("{ .reg .u64 t; cvta.to.shared.u64 t, %1; cvt.u32.u64 %0, t; }" : "=r"(a) : "l"(p));
    return a;
}
__device__ __forceinline__ void cp16(uint32_t dst, const void* src) {
    asm volatile("cp.async.cg.shared.global [%0], [%1], 16;\n" :: "r"(dst), "l"(src) : "memory");
}
__device__ __forceinline__ void cp_commit() {
    asm volatile("cp.async.commit_group;\n" ::: "memory");
}
template <int N> __device__ __forceinline__ void cp_wait() {
    asm volatile("cp.async.wait_group %0;\n" :: "n"(N) : "memory");
}
__device__ __forceinline__ void ldmx4(uint32_t& r0, uint32_t& r1, uint32_t& r2, uint32_t& r3,
                                      uint32_t addr) {
    asm volatile("ldmatrix.sync.aligned.m8n8.x4.shared.b16 {%0,%1,%2,%3}, [%4];"
                 : "=r"(r0), "=r"(r1), "=r"(r2), "=r"(r3) : "r"(addr));
}
// fp16 MMA, f32 accumulate: D(16x8) += A(16x16) x B(16x8)
__device__ __forceinline__ void mma_f16(float c[4],
    uint32_t a0, uint32_t a1, uint32_t a2, uint32_t a3, uint32_t b0, uint32_t b1)
{
    asm volatile(
        "mma.sync.aligned.m16n8k16.row.col.f32.f16.f16.f32 "
        "{%0,%1,%2,%3}, {%4,%5,%6,%7}, {%8,%9}, {%0,%1,%2,%3};\n"
        : "+f"(c[0]), "+f"(c[1]), "+f"(c[2]), "+f"(c[3])
        : "r"(a0), "r"(a1), "r"(a2), "r"(a3), "r"(b0), "r"(b1));
}

struct GArgs {
    const __half* A[3];
    const __half* W[3];
    const float*  b[3];
    void*         C[3];
    int epi[3];               // 0: +bias  1: tanh(+bias)*ps  3: LN-affine+residual
    int oh[3];                // 1: store output as fp16
    const float* ps;          // epi1
    const float* resid;       // epi3: x
    const float2* stats;      // epi3: (rstd, mu*rstd)
    const float* gWo;         // epi3
};

// ---------------- GEMM (fp16 in, f32 acc, z-batched, runtime epilogue) ----------------
// C[z][M,1024] = A[z] @ W[z]^T.  W is [N rows, K cols], both fp16.
// 256 threads (8 warps), warp tile 32x64, 3-stage cp.async, XOR-swizzled ldmatrix.
__global__ void __launch_bounds__(256, 2)
gemm_rt(const GArgs args)
{
    extern __shared__ char smem[];
    const uint32_t tileBase = smem_u32(smem);

    const int z = blockIdx.z;
    const __half* A    = args.A[z];
    const __half* WT   = args.W[z];
    const float*  bias = args.b[z];
    void*         C    = args.C[z];
    const int     epi  = args.epi[z];
    const int     oh   = args.oh[z];

    const int tid  = threadIdx.x;
    const int wid  = tid >> 5;
    const int lane = tid & 31;
    const int wm   = wid >> 1;
    const int wn   = wid & 1;
    const int g    = lane >> 2;
    const int tg   = lane & 3;

    const long bm0 = (long)blockIdx.y * MT;
    const int  bn0 = blockIdx.x * NT;

    const __half* Abase = A  + bm0 * K_DIM;
    const __half* Bbase = WT + (long)bn0 * K_DIM;

    // rows 128B apart (64 fp16), 8 chunks of 16B, XOR-swizzled by row&7
    const uint32_t rsw   = lane & 7;
    const uint32_t aoff0 = (uint32_t)((wm * 32 + ((lane >> 3) & 1) * 8 + (lane & 7)) * 128);
    const uint32_t hbitA = (lane >> 4) & 1;
    const uint32_t boff0 = (uint32_t)((wn * 64 + ((lane >> 4) & 1) * 8 + (lane & 7)) * 128) + 16384u;
    const uint32_t hbitB = (lane >> 3) & 1;

    auto fill = [&](int s) {
        const uint32_t buf = tileBase + (uint32_t)(s % STAGES) * STAGE_BYTES;
        const int k0 = s * KT;
        #pragma unroll
        for (int i = 0; i < 4; i++) {          // A: 128 rows x 8 chunks (16B = 8 fp16)
            int o = tid + 256 * i;
            int row = o >> 3, c = o & 7;
            cp16(buf + (uint32_t)(row * 128 + ((c ^ (row & 7)) << 4)),
                 Abase + (long)row * K_DIM + k0 + c * 8);
        }
        #pragma unroll
        for (int i = 0; i < 4; i++) {          // B
            int o = tid + 256 * i;
            int row = o >> 3, c = o & 7;
            cp16(buf + 16384u + (uint32_t)(row * 128 + ((c ^ (row & 7)) << 4)),
                 Bbase + (long)row * K_DIM + k0 + c * 8);
        }
        cp_commit();
    };

    float acc[2][8][4];
    #pragma unroll
    for (int i = 0; i < 2; i++)
        #pragma unroll
        for (int j = 0; j < 8; j++)
            #pragma unroll
            for (int k = 0; k < 4; k++)
                acc[i][j][k] = 0.f;

    fill(0);
    fill(1);

    #pragma unroll 1
    for (int kt = 0; kt < KITERS; kt++) {
        if (kt < KITERS - 1) cp_wait<1>(); else cp_wait<0>();
        __syncthreads();
        if (kt < KITERS - 2) fill(kt + 2);

        const uint32_t sbase = tileBase + (uint32_t)(kt % STAGES) * STAGE_BYTES;
        #pragma unroll
        for (int kk = 0; kk < 4; kk++) {       // K=16 per kk
            uint32_t af[2][4], bf[8][2];
            const uint32_t cA = ((uint32_t)(kk * 2) + hbitA) ^ rsw;
            const uint32_t cB = ((uint32_t)(kk * 2) + hbitB) ^ rsw;
            ldmx4(af[0][0], af[0][1], af[0][2], af[0][3], sbase + aoff0 + (cA << 4));
            ldmx4(af[1][0], af[1][1], af[1][2], af[1][3], sbase + aoff0 + 2048u + (cA << 4));
            #pragma unroll
            for (int q = 0; q < 4; q++)
                ldmx4(bf[2 * q][0], bf[2 * q][1], bf[2 * q + 1][0], bf[2 * q + 1][1],
                      sbase + boff0 + (uint32_t)(q * 2048) + (cB << 4));
            #pragma unroll
            for (int im = 0; im < 2; im++)
                #pragma unroll
                for (int in = 0; in < 8; in++)
                    mma_f16(acc[im][in],
                            af[im][0], af[im][1], af[im][2], af[im][3],
                            bf[in][0], bf[in][1]);
        }
    }

    // Epilogue
    #pragma unroll
    for (int im = 0; im < 2; im++) {
        #pragma unroll
        for (int in = 0; in < 8; in++) {
            const int col = bn0 + wn * 64 + in * 8 + 2 * tg;
            const float b0 = __ldg(bias + col);
            const float b1 = __ldg(bias + col + 1);
            #pragma unroll
            for (int h = 0; h < 2; h++) {
                const long row = bm0 + wm * 32 + im * 16 + g + h * 8;
                float v0, v1;
                if (epi == 3) {
                    const float2 st = __ldg(args.stats + row);
                    v0 = st.x * acc[im][in][2 * h + 0] - st.y * __ldg(args.gWo + col) + b0
                         + args.resid[row * N_DIM + col];
                    v1 = st.x * acc[im][in][2 * h + 1] - st.y * __ldg(args.gWo + col + 1) + b1
                         + args.resid[row * N_DIM + col + 1];
                } else {
                    v0 = acc[im][in][2 * h + 0] + b0;
                    v1 = acc[im][in][2 * h + 1] + b1;
                    if (epi == 1) {
                        v0 = tanhf(v0) * __ldg(args.ps + col);
                        v1 = tanhf(v1) * __ldg(args.ps + col + 1);
                    }
                }
                if (oh) {
                    *(__half2*)((__half*)C + row * N_DIM + col) = __floats2half2_rn(v0, v1);
                } else {
                    *(float2*)((float*)C + row * N_DIM + col) = make_float2(v0, v1);
                }
            }
        }
    }
}

// ---------------- prep kernels ----------------
struct W4 { const float* w[4]; };

// transpose + convert to fp16 -> WT slots {0,1,2,5}
__global__ void __launch_bounds__(256)
wtrans_all_k(const W4 ws, __half* __restrict__ WT)
{
    __shared__ float t[32][33];
    static const int slot[4] = {0, 1, 2, 5};
    const float* W = ws.w[blockIdx.z];
    __half* D = WT + (long)slot[blockIdx.z] * 1048576;
    int bx = blockIdx.x * 32, by = blockIdx.y * 32;
    #pragma unroll
    for (int i = threadIdx.y; i < 32; i += 8)
        t[i][threadIdx.x] = W[(by + i) * 1024 + bx + threadIdx.x];
    __syncthreads();
    #pragma unroll
    for (int i = threadIdx.y; i < 32; i += 8)
        D[(bx + i) * 1024 + by + threadIdx.x] = __float2half_rn(t[threadIdx.x][i]);
}

// f32 -> fp16 (8 elems/thread); blockIdx.y selects src/dst pair
__global__ void __launch_bounds__(256)
cvt2_h_k(const float* __restrict__ s0, __half* __restrict__ d0,
         const float* __restrict__ s1, __half* __restrict__ d1)
{
    const float* s = blockIdx.y ? s1 : s0;
    __half* d = blockIdx.y ? d1 : d0;
    long i = ((long)blockIdx.x * 256 + threadIdx.x) * 8;
    float4 v0 = *(const float4*)(s + i);
    float4 v1 = *(const float4*)(s + i + 4);
    __half2 h[4];
    h[0] = __floats2half2_rn(v0.x, v0.y);
    h[1] = __floats2half2_rn(v0.z, v0.w);
    h[2] = __floats2half2_rn(v1.x, v1.y);
    h[3] = __floats2half2_rn(v1.z, v1.w);
    *(uint4*)(d + i) = *(uint4*)h;
}

__global__ void __launch_bounds__(256)
cvt_h_k(const float* __restrict__ s, __half* __restrict__ d)
{
    long i = ((long)blockIdx.x * 256 + threadIdx.x) * 8;
    float4 v0 = *(const float4*)(s + i);
    float4 v1 = *(const float4*)(s + i + 4);
    __half2 h[4];
    h[0] = __floats2half2_rn(v0.x, v0.y);
    h[1] = __floats2half2_rn(v0.z, v0.w);
    h[2] = __floats2half2_rn(v1.x, v1.y);
    h[3] = __floats2half2_rn(v1.z, v1.w);
    *(uint4*)(d + i) = *(uint4*)h;
}

// GEMVs from fp16 transposed weights: one warp per output column, 4 warps/CTA.
__global__ void __launch_bounds__(128)
gemv_prep_k(const __half* __restrict__ WoT, const __half* __restrict__ WkpT,
            const __half* __restrict__ WqpT,
            const float* __restrict__ g, const float* __restrict__ b,
            const float* __restrict__ bo,
            const float* __restrict__ bk, const float* __restrict__ bkp,
            const float* __restrict__ bq, const float* __restrict__ bqp,
            float* __restrict__ gWo, float* __restrict__ bWoBo,
            float* __restrict__ bck, float* __restrict__ bcq)
{
    const int lane = threadIdx.x & 31;
    const int col  = blockIdx.x * 4 + (threadIdx.x >> 5);
    const __half* wo  = WoT  + (long)col * 1024;
    const __half* wkp = WkpT + (long)col * 1024;
    const __half* wqp = WqpT + (long)col * 1024;
    float a1 = 0.f, a2 = 0.f, a3 = 0.f, a4 = 0.f;
    #pragma unroll 8
    for (int d = lane; d < 1024; d += 32) {
        float w = __half2float(wo[d]);
        a1 = fmaf(__ldg(g + d), w, a1);
        a2 = fmaf(__ldg(b + d), w, a2);
        a3 = fmaf(__ldg(bk + d), __half2float(wkp[d]), a3);
        a4 = fmaf(__ldg(bq + d), __half2float(wqp[d]), a4);
    }
    #pragma unroll
    for (int o = 16; o; o >>= 1) {
        a1 += __shfl_xor_sync(0xffffffffu, a1, o);
        a2 += __shfl_xor_sync(0xffffffffu, a2, o);
        a3 += __shfl_xor_sync(0xffffffffu, a3, o);
        a4 += __shfl_xor_sync(0xffffffffu, a4, o);
    }
    if (lane == 0) {
        gWo[col]   = a1;
        bWoBo[col] = a2 + bo[col];
        bck[col]   = a3 + bkp[col];
        bcq[col]   = a4 + bqp[col];
    }
}

// ---------------- bind + chunk scan + row stats + gamma fold (V fp16 in, R fp16 out) ----------------
__global__ void __launch_bounds__(256)
bind_scan_k(const __half* __restrict__ V, const float* __restrict__ KP,
            const float* __restrict__ QP, const float* __restrict__ lng,
            __half* __restrict__ R, float2* __restrict__ stats)
{
    __shared__ float2 part[64][8];
    const float inv = 0.03125f;  // 1/sqrt(1024)
    const int tid = threadIdx.x;
    const int lane = tid & 31, w = tid >> 5;
    long idx = (long)blockIdx.x * 64 * 1024 + tid * 4;
    float4 mr = make_float4(0.f, 0.f, 0.f, 0.f);
    float4 mi = make_float4(0.f, 0.f, 0.f, 0.f);
    const float4 gv = *(const float4*)(lng + tid * 4);

    #pragma unroll 4
    for (int s = 0; s < 64; s++, idx += 1024) {
        uint2 vpk = *(const uint2*)(V + idx);
        float2 va = __half22float2(*(__half2*)&vpk.x);
        float2 vb = __half22float2(*(__half2*)&vpk.y);
        float4 v = make_float4(va.x, va.y, vb.x, vb.y);
        float4 kp = *(const float4*)(KP + idx);
        float4 qp = *(const float4*)(QP + idx);
        float4 out;
        float sk, ck, sq, cq;
        __sincosf(kp.x, &sk, &ck);
        mr.x = fmaf(v.x, ck, mr.x); mi.x = fmaf(v.x, sk, mi.x);
        __sincosf(qp.x, &sq, &cq);
        out.x = (mr.x * cq + mi.x * sq) * inv;
        __sincosf(kp.y, &sk, &ck);
        mr.y = fmaf(v.y, ck, mr.y); mi.y = fmaf(v.y, sk, mi.y);
        __sincosf(qp.y, &sq, &cq);
        out.y = (mr.y * cq + mi.y * sq) * inv;
        __sincosf(kp.z, &sk, &ck);
        mr.z = fmaf(v.z, ck, mr.z); mi.z = fmaf(v.z, sk, mi.z);
        __sincosf(qp.z, &sq, &cq);
        out.z = (mr.z * cq + mi.z * sq) * inv;
        __sincosf(kp.w, &sk, &ck);
        mr.w = fmaf(v.w, ck, mr.w); mi.w = fmaf(v.w, sk, mi.w);
        __sincosf(qp.w, &sq, &cq);
        out.w = (mr.w * cq + mi.w * sq) * inv;

        float rs = out.x + out.y + out.z + out.w;
        float rq = out.x * out.x + out.y * out.y + out.z * out.z + out.w * out.w;
        #pragma unroll
        for (int o = 16; o; o >>= 1) {
            rs += __shfl_xor_sync(0xffffffffu, rs, o);
            rq += __shfl_xor_sync(0xffffffffu, rq, o);
        }
        if (lane == 0) part[s][w] = make_float2(rs, rq);

        __half2 h0 = __floats2half2_rn(out.x * gv.x, out.y * gv.y);
        __half2 h1 = __floats2half2_rn(out.z * gv.z, out.w * gv.w);
        uint2 pk = make_uint2(*(uint32_t*)&h0, *(uint32_t*)&h1);
        *(uint2*)(R + idx) = pk;
    }
    __syncthreads();
    if (tid < 64) {
        float S = 0.f, Q = 0.f;
        #pragma unroll
        for (int i = 0; i < 8; i++) { S += part[tid][i].x; Q += part[tid][i].y; }
        float mu = S * (1.f / 1024.f);
        float var = Q * (1.f / 1024.f) - mu * mu;
        float rstd = rsqrtf(var + 1e-5f);
        stats[blockIdx.x * 64 + tid] = make_float2(rstd, mu * rstd);
    }
}

extern "C" void kernel_launch(void* const* d_in, const int* in_sizes, int n_in,
                              void* d_out, int out_size)
{
    const float* x   = (const float*)d_in[0];
    const float* Wk  = (const float*)d_in[1];
    const float* bk  = (const float*)d_in[2];
    const float* Wv  = (const float*)d_in[3];
    const float* bv  = (const float*)d_in[4];
    const float* Wq  = (const float*)d_in[5];
    const float* bq  = (const float*)d_in[6];
    const float* Wkp = (const float*)d_in[7];
    const float* bkp = (const float*)d_in[8];
    const float* Wqp = (const float*)d_in[9];
    const float* bqp = (const float*)d_in[10];
    const float* ps  = (const float*)d_in[11];
    const float* lng = (const float*)d_in[12];
    const float* lnb = (const float*)d_in[13];
    const float* Wo  = (const float*)d_in[14];
    const float* bo  = (const float*)d_in[15];
    float* out = (float*)d_out;

    const int M = in_sizes[0] / 1024;  // 32768

    float *pKP, *pQP;
    __half *pVh, *pR, *pX, *pWT, *pWkR, *pWqR;
    float *pgWo, *pbWoBo, *pbck, *pbcq, *pzero;
    float2* pStats;
    cudaGetSymbolAddress((void**)&pVh,  g_Vh);
    cudaGetSymbolAddress((void**)&pKP,  g_KP);
    cudaGetSymbolAddress((void**)&pQP,  g_QP);
    cudaGetSymbolAddress((void**)&pR,   g_R);
    cudaGetSymbolAddress((void**)&pX,   g_X);
    cudaGetSymbolAddress((void**)&pWT,  g_WT);
    cudaGetSymbolAddress((void**)&pWkR, g_WkR);
    cudaGetSymbolAddress((void**)&pWqR, g_WqR);
    cudaGetSymbolAddress((void**)&pStats, g_stats);
    cudaGetSymbolAddress((void**)&pgWo, g_gWo);
    cudaGetSymbolAddress((void**)&pbWoBo, g_bWoBo);
    cudaGetSymbolAddress((void**)&pbck, g_bck);
    cudaGetSymbolAddress((void**)&pbcq, g_bcq);
    cudaGetSymbolAddress((void**)&pzero, g_zero);

    cudaFuncSetAttribute(gemm_rt, cudaFuncAttributeMaxDynamicSharedMemorySize, SMEM_TOTAL);

    // prep: transpose+cvt (Wv, Wkp, Wqp, Wo); cvt Wk+Wq (merged), X; bias GEMVs
    W4 ws;
    ws.w[0] = Wv; ws.w[1] = Wkp; ws.w[2] = Wqp; ws.w[3] = Wo;
    wtrans_all_k<<<dim3(32, 32, 4), dim3(32, 8)>>>(ws, pWT);
    cvt2_h_k<<<dim3(512, 2), 256>>>(Wk, pWkR, Wq, pWqR);
    cvt_h_k<<<NELEM / 2048, 256>>>(x, pX);
    gemv_prep_k<<<256, 128>>>(pWT + 5 * 1048576, pWT + 1 * 1048576, pWT + 2 * 1048576,
                              lng, lnb, bo, bk, bkp, bq, bqp,
                              pgWo, pbWoBo, pbck, pbcq);

    GArgs a{};
    a.ps = ps; a.resid = x; a.stats = pStats; a.gWo = pgWo;

    // Weight composition: WckT = WkpT x WkR -> slot3 ; WcqT = WqpT x WqR -> slot4 (fp16 out)
    a.A[0] = pWT + 1 * 1048576; a.A[1] = pWT + 2 * 1048576; a.A[2] = a.A[1];
    a.W[0] = pWkR;              a.W[1] = pWqR;              a.W[2] = a.W[1];
    a.b[0] = pzero; a.b[1] = pzero; a.b[2] = pzero;
    a.C[0] = pWT + 3 * 1048576; a.C[1] = pWT + 4 * 1048576; a.C[2] = a.C[1];
    a.epi[0] = 0; a.epi[1] = 0; a.epi[2] = 0;
    a.oh[0] = 1; a.oh[1] = 1; a.oh[2] = 1;
    gemm_rt<<<dim3(8, 8, 2), 256, SMEM_TOTAL>>>(a);

    // Big batch: V(fp16) = X@WvT+bv ; KP = tanh(X@WckT+bck)*ps ; QP = tanh(X@WcqT+bcq)*ps
    a.A[0] = pX; a.A[1] = pX; a.A[2] = pX;
    a.W[0] = pWT + 0 * 1048576; a.W[1] = pWT + 3 * 1048576; a.W[2] = pWT + 4 * 1048576;
    a.b[0] = bv; a.b[1] = pbck; a.b[2] = pbcq;
    a.C[0] = pVh; a.C[1] = pKP; a.C[2] = pQP;
    a.epi[0] = 0; a.epi[1] = 1; a.epi[2] = 1;
    a.oh[0] = 1; a.oh[1] = 0; a.oh[2] = 0;
    gemm_rt<<<dim3(N_DIM / NT, M / MT, 3), 256, SMEM_TOTAL>>>(a);

    bind_scan_k<<<M / 64, 256>>>(pVh, pKP, pQP, lng, pR, pStats);

    // Output GEMM with fused LayerNorm-affine + residual
    a.A[0] = pR; a.A[1] = pR; a.A[2] = pR;
    a.W[0] = pWT + 5 * 1048576; a.W[1] = a.W[0]; a.W[2] = a.W[0];
    a.b[0] = pbWoBo; a.b[1] = pbWoBo; a.b[2] = pbWoBo;
    a.C[0] = out; a.C[1] = out; a.C[2] = out;
    a.epi[0] = 3; a.epi[1] = 3; a.epi[2] = 3;
    a.oh[0] = 0; a.oh[1] = 0; a.oh[2] = 0;
    gemm_rt<<<dim3(N_DIM / NT, M / MT, 1), 256, SMEM_TOTAL>>>(a);
}